// round 12
// baseline (speedup 1.0000x reference)
#include <cuda_runtime.h>
#include <cuda_fp16.h>
#include <cstdint>
#include <math.h>

// Problem constants
#define B_  2
#define S_  2048
#define D_  2048
#define H_  16
#define DH  128
#define MROWS (B_ * S_)          // 4096

// ---------------------------------------------------------------------------
// Scratch (static __device__ arrays; no allocation anywhere)
// ---------------------------------------------------------------------------
__device__ float g_tq[(size_t)MROWS * D_];
__device__ float g_tk[(size_t)MROWS * D_];
__device__ float g_tv[(size_t)MROWS * D_];

__device__ __align__(256) __half g_xh [(size_t)MROWS * D_];
__device__ __align__(256) __half g_xl [(size_t)MROWS * D_];
__device__ __align__(256) __half g_qwh[(size_t)D_ * D_];
__device__ __align__(256) __half g_qwl[(size_t)D_ * D_];
__device__ __align__(256) __half g_kwh[(size_t)D_ * D_];
__device__ __align__(256) __half g_kwl[(size_t)D_ * D_];
__device__ __align__(256) __half g_vwh[(size_t)D_ * D_];
__device__ __align__(256) __half g_vwl[(size_t)D_ * D_];
__device__ __align__(256) __half g_owh[(size_t)D_ * D_];
__device__ __align__(256) __half g_owl[(size_t)D_ * D_];
__device__ __align__(256) __half g_qh [(size_t)B_ * H_ * S_ * DH];
__device__ __align__(256) __half g_ql [(size_t)B_ * H_ * S_ * DH];
__device__ __align__(256) __half g_kh [(size_t)B_ * H_ * S_ * DH];
__device__ __align__(256) __half g_kl [(size_t)B_ * H_ * S_ * DH];
__device__ __align__(256) __half g_vth[(size_t)B_ * H_ * DH * S_];   // V^T [B,H,Dh,S]
__device__ __align__(256) __half g_vtl[(size_t)B_ * H_ * DH * S_];
__device__ __align__(256) __half g_ctxh[(size_t)MROWS * D_];
__device__ __align__(256) __half g_ctxl[(size_t)MROWS * D_];

// ---------------------------------------------------------------------------
// Helpers (all sm_80-era instructions: valid on base sm_103 target)
// ---------------------------------------------------------------------------
#define SWZ(x) ((x) ^ (((x) >> 3) & 0x70))

#define LDSM4(r, addr) \
    asm volatile("ldmatrix.sync.aligned.m8n8.x4.shared.b16 {%0,%1,%2,%3}, [%4];" \
        : "=r"((r)[0]), "=r"((r)[1]), "=r"((r)[2]), "=r"((r)[3]) : "r"(addr))

// fp32-accumulate MMA (main hi*hi pass)
#define MMA(d, a, b0, b1) \
    asm volatile("mma.sync.aligned.m16n8k16.row.col.f32.f16.f16.f32 " \
        "{%0,%1,%2,%3},{%4,%5,%6,%7},{%8,%9},{%0,%1,%2,%3};" \
        : "+f"((d)[0]), "+f"((d)[1]), "+f"((d)[2]), "+f"((d)[3]) \
        : "r"((a)[0]), "r"((a)[1]), "r"((a)[2]), "r"((a)[3]), "r"(b0), "r"(b1))

// fp16-accumulate MMA (2x rate; used for the small correction passes)
#define MMA16(d, a, b0, b1) \
    asm volatile("mma.sync.aligned.m16n8k16.row.col.f16.f16.f16.f16 " \
        "{%0,%1},{%2,%3,%4,%5},{%6,%7},{%0,%1};" \
        : "+r"((d)[0]), "+r"((d)[1]) \
        : "r"((a)[0]), "r"((a)[1]), "r"((a)[2]), "r"((a)[3]), "r"(b0), "r"(b1))

#define CP16(dst, src) \
    asm volatile("cp.async.cg.shared.global [%0], [%1], 16;" :: "r"(dst), "l"(src))
#define CP_COMMIT() asm volatile("cp.async.commit_group;" ::: "memory")
#define CP_WAIT0()  asm volatile("cp.async.wait_group 0;"  ::: "memory")

__device__ __forceinline__ void split2(float x, __half& h, __half& l) {
    h = __float2half(x);
    l = __float2half(x - __half2float(h));
}
__device__ __forceinline__ uint32_t packh2(__half a, __half b) {
    __half2 t; t.x = a; t.y = b;
    return *(uint32_t*)&t;
}
__device__ __forceinline__ float2 h2f2(uint32_t u) {
    return __half22float2(*(__half2*)&u);
}

// ---------------------------------------------------------------------------
// fp16-split HMMA GEMM.  C = scale * (A @ B^T) + bias, fp32 out
//   hi*hi in fp32 accum; hi*lo + lo*hi share one fp16x2 accum (2x-rate MMA).
// Tile 128x64, BK=64; 256 threads / 8 warps of 32x32; 2 CTAs/SM.
// smem: 2 stages x [Ah 16K | Al 16K | Bh 8K | Bl 8K] = 96KB.
// ---------------------------------------------------------------------------
#define GSTAGE 49152

__global__ __launch_bounds__(256, 2)
void gemm_hs(const __half* __restrict__ Ah, const __half* __restrict__ Al,
             const __half* __restrict__ Bh, const __half* __restrict__ Bl,
             float* __restrict__ C, int K, int ldb,
             const float* __restrict__ bias, float scale)
{
    extern __shared__ char smem[];
    const uint32_t sb = (uint32_t)__cvta_generic_to_shared(smem);

    const int tid = threadIdx.x, wid = tid >> 5, lane = tid & 31;
    const long bm = (long)blockIdx.y * 128;
    const long bn = (long)blockIdx.x * 64;

    // A staging: 128 rows, 2 threads/row, 4 chunks each
    const int arow = tid >> 1;
    const int ac0  = (tid & 1) * 4;
    uint32_t aoff[4];
#pragma unroll
    for (int i = 0; i < 4; i++)
        aoff[i] = SWZ((uint32_t)(arow * 128 + (ac0 + i) * 16));

    // B staging: 64 rows, 4 threads/row, 2 chunks each
    const int brow = tid >> 2;
    const int bc0  = (tid & 3) * 2;
    uint32_t boff[2];
#pragma unroll
    for (int i = 0; i < 2; i++)
        boff[i] = SWZ((uint32_t)(brow * 128 + (bc0 + i) * 16));

    const int nk = K / 64;

    // prologue: stage buffer 0
    {
        const __half* pa  = Ah + (bm + arow) * (long)K + ac0 * 8;
        const __half* pl  = Al + (bm + arow) * (long)K + ac0 * 8;
        const __half* pb  = Bh + (bn + brow) * (long)ldb + bc0 * 8;
        const __half* pbl = Bl + (bn + brow) * (long)ldb + bc0 * 8;
#pragma unroll
        for (int i = 0; i < 4; i++) {
            CP16(sb + aoff[i],         pa + i * 8);
            CP16(sb + 16384 + aoff[i], pl + i * 8);
        }
#pragma unroll
        for (int i = 0; i < 2; i++) {
            CP16(sb + 32768 + boff[i], pb + i * 8);
            CP16(sb + 40960 + boff[i], pbl + i * 8);
        }
        CP_COMMIT();
    }

    float acc[2][4][4];
    uint32_t acc16[2][4][2];
#pragma unroll
    for (int a = 0; a < 2; a++)
#pragma unroll
        for (int b = 0; b < 4; b++) {
#pragma unroll
            for (int c = 0; c < 4; c++) acc[a][b][c] = 0.f;
            acc16[a][b][0] = 0u; acc16[a][b][1] = 0u;
        }

    const int m0 = (wid & 3) * 32;          // 4 warp-rows
    const int n0 = (wid >> 2) * 32;         // 2 warp-cols
    const int rA = lane & 15;
    const int cA = lane >> 4;
    const int rB = ((lane >> 1) & 8) + (lane & 7);
    const int cB = (lane >> 3) & 1;

    for (int kt = 0; kt < nk; ++kt) {
        const int s = kt & 1;
        CP_WAIT0();
        __syncthreads();

        if (kt + 1 < nk) {
            const uint32_t db = sb + (s ^ 1) * GSTAGE;
            const __half* pa  = Ah + (bm + arow) * (long)K + (kt + 1) * 64 + ac0 * 8;
            const __half* pl  = Al + (bm + arow) * (long)K + (kt + 1) * 64 + ac0 * 8;
            const __half* pb  = Bh + (bn + brow) * (long)ldb + (kt + 1) * 64 + bc0 * 8;
            const __half* pbl = Bl + (bn + brow) * (long)ldb + (kt + 1) * 64 + bc0 * 8;
#pragma unroll
            for (int i = 0; i < 4; i++) {
                CP16(db + aoff[i],         pa + i * 8);
                CP16(db + 16384 + aoff[i], pl + i * 8);
            }
#pragma unroll
            for (int i = 0; i < 2; i++) {
                CP16(db + 32768 + boff[i], pb + i * 8);
                CP16(db + 40960 + boff[i], pbl + i * 8);
            }
            CP_COMMIT();
        }

        const uint32_t ba = sb + (uint32_t)s * GSTAGE;
#pragma unroll
        for (int ks = 0; ks < 4; ks++) {
            uint32_t ah[2][4], al[2][4], bh[2][4], bl[2][4];
#pragma unroll
            for (int mt = 0; mt < 2; mt++) {
                const uint32_t addr = ba +
                    SWZ((uint32_t)((m0 + mt * 16 + rA) * 128 + (ks * 2 + cA) * 16));
                LDSM4(ah[mt], addr);
                LDSM4(al[mt], addr + 16384);
            }
#pragma unroll
            for (int p = 0; p < 2; p++) {
                const uint32_t addr = ba + 32768 +
                    SWZ((uint32_t)((n0 + p * 16 + rB) * 128 + (ks * 2 + cB) * 16));
                LDSM4(bh[p], addr);
                LDSM4(bl[p], addr + 8192);
            }
            // pass 1: hi*hi (fp32 acc)
#pragma unroll
            for (int mt = 0; mt < 2; mt++)
#pragma unroll
                for (int nt = 0; nt < 4; nt++) {
                    const int p = nt >> 1, q = (nt & 1) * 2;
                    MMA(acc[mt][nt], ah[mt], bh[p][q], bh[p][q + 1]);
                }
            // pass 2: hi*lo (fp16 acc)
#pragma unroll
            for (int mt = 0; mt < 2; mt++)
#pragma unroll
                for (int nt = 0; nt < 4; nt++) {
                    const int p = nt >> 1, q = (nt & 1) * 2;
                    MMA16(acc16[mt][nt], ah[mt], bl[p][q], bl[p][q + 1]);
                }
            // pass 3: lo*hi (fp16 acc)
#pragma unroll
            for (int mt = 0; mt < 2; mt++)
#pragma unroll
                for (int nt = 0; nt < 4; nt++) {
                    const int p = nt >> 1, q = (nt & 1) * 2;
                    MMA16(acc16[mt][nt], al[mt], bh[p][q], bh[p][q + 1]);
                }
        }
    }

    const int g = lane >> 2, t = lane & 3;
#pragma unroll
    for (int mt = 0; mt < 2; mt++) {
        const long r0 = bm + m0 + mt * 16 + g;
#pragma unroll
        for (int nt = 0; nt < 4; nt++) {
            const long col = bn + n0 + nt * 8 + 2 * t;
            const float2 u = h2f2(acc16[mt][nt][0]);
            const float2 w = h2f2(acc16[mt][nt][1]);
            float c0 = (acc[mt][nt][0] + u.x) * scale;
            float c1 = (acc[mt][nt][1] + u.y) * scale;
            float c2 = (acc[mt][nt][2] + w.x) * scale;
            float c3 = (acc[mt][nt][3] + w.y) * scale;
            if (bias) {
                const float b0 = __ldg(bias + col), b1 = __ldg(bias + col + 1);
                c0 += b0; c1 += b1; c2 += b0; c3 += b1;
            }
            *(float2*)(C + r0 * (long)D_ + col)       = make_float2(c0, c1);
            *(float2*)(C + (r0 + 8) * (long)D_ + col) = make_float2(c2, c3);
        }
    }
}

// ---------------------------------------------------------------------------
// Flash attention: per CTA = 128 Q rows x one (b,h).  (unchanged from R10)
// smem: Q 64K | Kbuf 2x32K | Vbuf 2x32K = 192K.
// ---------------------------------------------------------------------------
#define NKV (S_ / 64)     // 32 chunks

__global__ __launch_bounds__(256, 1)
void flash_kernel(const __half* __restrict__ Qh, const __half* __restrict__ Ql,
                  const __half* __restrict__ Kh, const __half* __restrict__ Kl,
                  const __half* __restrict__ Vth, const __half* __restrict__ Vtl,
                  __half* __restrict__ Ch, __half* __restrict__ Cl)
{
    extern __shared__ char smem[];
    const uint32_t sb = (uint32_t)__cvta_generic_to_shared(smem);

    const int tid = threadIdx.x, wid = tid >> 5, lane = tid & 31;
    const int qt = blockIdx.x;
    const int bh = blockIdx.y;
    const int b  = bh >> 4, h = bh & 15;

    const __half* Qhp = Qh + ((long)bh * S_ + (long)qt * 128) * DH;
    const __half* Qlp = Ql + ((long)bh * S_ + (long)qt * 128) * DH;
    const __half* Khp = Kh + (long)bh * S_ * DH;
    const __half* Klp = Kl + (long)bh * S_ * DH;
    const __half* Vhp = Vth + (long)bh * DH * S_;
    const __half* Vlp = Vtl + (long)bh * DH * S_;

    const uint32_t KBUF0 = 65536, VBUF0 = 131072;

    {
        const int r = tid >> 1, c0 = (tid & 1) * 8;
        const __half* s1 = Qhp + (long)r * DH;
        const __half* s2 = Qlp + (long)r * DH;
#pragma unroll
        for (int j = 0; j < 8; j++) {
            const int c = c0 + j;
            const uint32_t d = sb + ((c >= 8) ? 16384u : 0u) +
                               SWZ((uint32_t)(r * 128 + (c & 7) * 16));
            CP16(d,          s1 + c * 8);
            CP16(d + 32768u, s2 + c * 8);
        }
    }
    auto stageKV = [&](int it, uint32_t kdst, uint32_t vdst) {
        {
            const int r = tid >> 2, c0 = (tid & 3) * 4;
            const __half* s1 = Khp + ((long)it * 64 + r) * DH;
            const __half* s2 = Klp + ((long)it * 64 + r) * DH;
#pragma unroll
            for (int j = 0; j < 4; j++) {
                const int c = c0 + j;
                const uint32_t d = kdst + ((c >= 8) ? 8192u : 0u) +
                                   SWZ((uint32_t)(r * 128 + (c & 7) * 16));
                CP16(d,          s1 + c * 8);
                CP16(d + 16384u, s2 + c * 8);
            }
        }
        {
            const int dd = tid >> 1, c0 = (tid & 1) * 4;
            const __half* s1 = Vhp + (long)dd * S_ + it * 64;
            const __half* s2 = Vlp + (long)dd * S_ + it * 64;
#pragma unroll
            for (int j = 0; j < 4; j++) {
                const int c = c0 + j;
                const uint32_t d = vdst + SWZ((uint32_t)(dd * 128 + c * 16));
                CP16(d,          s1 + c * 8);
                CP16(d + 16384u, s2 + c * 8);
            }
        }
    };
    stageKV(0, sb + KBUF0, sb + VBUF0);
    CP_COMMIT();

    const int wm = wid * 16;
    const int rA = lane & 15;
    const int cA = lane >> 4;
    const int rB = ((lane >> 1) & 8) + (lane & 7);
    const int cB = (lane >> 3) & 1;
    const int g = lane >> 2, t = lane & 3;

    float o[16][4];
    uint32_t o16a[16][2], o16b[16][2];
#pragma unroll
    for (int i = 0; i < 16; i++) {
#pragma unroll
        for (int j = 0; j < 4; j++) o[i][j] = 0.f;
        o16a[i][0] = 0u; o16a[i][1] = 0u;
        o16b[i][0] = 0u; o16b[i][1] = 0u;
    }
    float m0 = -INFINITY, m1 = -INFINITY, l0 = 0.f, l1 = 0.f;

    for (int it = 0; it < NKV; ++it) {
        const int s = it & 1;
        CP_WAIT0();
        __syncthreads();
        if (it + 1 < NKV) {
            const int s2 = s ^ 1;
            stageKV(it + 1, sb + KBUF0 + s2 * 32768u, sb + VBUF0 + s2 * 32768u);
            CP_COMMIT();
        }

        const uint32_t kbuf = sb + KBUF0 + (uint32_t)s * 32768u;
        const uint32_t vbuf = sb + VBUF0 + (uint32_t)s * 32768u;

        float sa[8][4];
        uint32_t sa16[8][2];
#pragma unroll
        for (int i = 0; i < 8; i++) {
#pragma unroll
            for (int j = 0; j < 4; j++) sa[i][j] = 0.f;
            sa16[i][0] = 0u; sa16[i][1] = 0u;
        }

#pragma unroll
        for (int ks = 0; ks < 8; ks++) {
            uint32_t ah[4], al[4], bh[4][4], bl[4][4];
            const uint32_t qa = sb + (ks >> 2) * 16384u +
                SWZ((uint32_t)((wm + rA) * 128 + ((ks & 3) * 2 + cA) * 16));
            LDSM4(ah, qa);
            LDSM4(al, qa + 32768u);
            const uint32_t kb2 = kbuf + (ks >> 2) * 8192u;
#pragma unroll
            for (int p = 0; p < 4; p++) {
                const uint32_t addr = kb2 +
                    SWZ((uint32_t)((p * 16 + rB) * 128 + ((ks & 3) * 2 + cB) * 16));
                LDSM4(bh[p], addr);
                LDSM4(bl[p], addr + 16384u);
            }
#pragma unroll
            for (int nt = 0; nt < 8; nt++) {
                const int p = nt >> 1, q = (nt & 1) * 2;
                MMA(sa[nt], ah, bh[p][q], bh[p][q + 1]);
            }
#pragma unroll
            for (int nt = 0; nt < 8; nt++) {
                const int p = nt >> 1, q = (nt & 1) * 2;
                MMA16(sa16[nt], ah, bl[p][q], bl[p][q + 1]);
            }
#pragma unroll
            for (int nt = 0; nt < 8; nt++) {
                const int p = nt >> 1, q = (nt & 1) * 2;
                MMA16(sa16[nt], al, bh[p][q], bh[p][q + 1]);
            }
        }

#pragma unroll
        for (int nt = 0; nt < 8; nt++) {
            const float2 u = h2f2(sa16[nt][0]);
            const float2 w = h2f2(sa16[nt][1]);
            sa[nt][0] += u.x; sa[nt][1] += u.y;
            sa[nt][2] += w.x; sa[nt][3] += w.y;
        }

        float nm0 = sa[0][0], nm1 = sa[0][2];
#pragma unroll
        for (int nt = 0; nt < 8; nt++) {
            nm0 = fmaxf(nm0, fmaxf(sa[nt][0], sa[nt][1]));
            nm1 = fmaxf(nm1, fmaxf(sa[nt][2], sa[nt][3]));
        }
        nm0 = fmaxf(nm0, __shfl_xor_sync(0xFFFFFFFFu, nm0, 1));
        nm0 = fmaxf(nm0, __shfl_xor_sync(0xFFFFFFFFu, nm0, 2));
        nm1 = fmaxf(nm1, __shfl_xor_sync(0xFFFFFFFFu, nm1, 1));
        nm1 = fmaxf(nm1, __shfl_xor_sync(0xFFFFFFFFu, nm1, 2));

        const float mn0 = fmaxf(m0, nm0), mn1 = fmaxf(m1, nm1);
        const float al0 = exp2f(m0 - mn0), al1 = exp2f(m1 - mn1);
        m0 = mn0; m1 = mn1;

        float rs0 = 0.f, rs1 = 0.f;
#pragma unroll
        for (int nt = 0; nt < 8; nt++) {
            sa[nt][0] = exp2f(sa[nt][0] - m0);
            sa[nt][1] = exp2f(sa[nt][1] - m0);
            sa[nt][2] = exp2f(sa[nt][2] - m1);
            sa[nt][3] = exp2f(sa[nt][3] - m1);
            rs0 += sa[nt][0] + sa[nt][1];
            rs1 += sa[nt][2] + sa[nt][3];
        }
        rs0 += __shfl_xor_sync(0xFFFFFFFFu, rs0, 1);
        rs0 += __shfl_xor_sync(0xFFFFFFFFu, rs0, 2);
        rs1 += __shfl_xor_sync(0xFFFFFFFFu, rs1, 1);
        rs1 += __shfl_xor_sync(0xFFFFFFFFu, rs1, 2);
        l0 = l0 * al0 + rs0;
        l1 = l1 * al1 + rs1;

        {
            const __half2 a0 = __half2half2(__float2half(al0));
            const __half2 a1 = __half2half2(__float2half(al1));
#pragma unroll
            for (int nt = 0; nt < 16; nt++) {
                o[nt][0] *= al0; o[nt][1] *= al0;
                o[nt][2] *= al1; o[nt][3] *= al1;
                __half2 ta0 = __hmul2(*(__half2*)&o16a[nt][0], a0);
                __half2 ta1 = __hmul2(*(__half2*)&o16a[nt][1], a1);
                __half2 tb0 = __hmul2(*(__half2*)&o16b[nt][0], a0);
                __half2 tb1 = __hmul2(*(__half2*)&o16b[nt][1], a1);
                o16a[nt][0] = *(uint32_t*)&ta0;
                o16a[nt][1] = *(uint32_t*)&ta1;
                o16b[nt][0] = *(uint32_t*)&tb0;
                o16b[nt][1] = *(uint32_t*)&tb1;
            }
        }

#pragma unroll
        for (int kb = 0; kb < 4; kb++) {
            uint32_t aPh[4], aPl[4];
            {
                const float p00 = sa[2 * kb][0],     p01 = sa[2 * kb][1];
                const float p10 = sa[2 * kb][2],     p11 = sa[2 * kb][3];
                const float q00 = sa[2 * kb + 1][0], q01 = sa[2 * kb + 1][1];
                const float q10 = sa[2 * kb + 1][2], q11 = sa[2 * kb + 1][3];
                __half hA, lA, hB, lB;
                split2(p00, hA, lA); split2(p01, hB, lB);
                aPh[0] = packh2(hA, hB); aPl[0] = packh2(lA, lB);
                split2(p10, hA, lA); split2(p11, hB, lB);
                aPh[1] = packh2(hA, hB); aPl[1] = packh2(lA, lB);
                split2(q00, hA, lA); split2(q01, hB, lB);
                aPh[2] = packh2(hA, hB); aPl[2] = packh2(lA, lB);
                split2(q10, hA, lA); split2(q11, hB, lB);
                aPh[3] = packh2(hA, hB); aPl[3] = packh2(lA, lB);
            }
#pragma unroll
            for (int pp = 0; pp < 8; pp++) {
                uint32_t vb[4], vbl[4];
                const uint32_t addr = vbuf +
                    SWZ((uint32_t)((pp * 16 + rB) * 128 + (kb * 2 + cB) * 16));
                LDSM4(vb, addr);
                LDSM4(vbl, addr + 16384u);
                MMA(o[pp * 2], aPh, vb[0], vb[1]);
                MMA16(o16a[pp * 2], aPh, vbl[0], vbl[1]);
                MMA16(o16b[pp * 2], aPl, vb[0], vb[1]);
                MMA(o[pp * 2 + 1], aPh, vb[2], vb[3]);
                MMA16(o16a[pp * 2 + 1], aPh, vbl[2], vbl[3]);
                MMA16(o16b[pp * 2 + 1], aPl, vb[2], vb[3]);
            }
        }
    }

    const float r0i = 1.0f / l0, r1i = 1.0f / l1;
    const long row0 = (long)b * S_ + (long)qt * 128 + wm + g;
    const long row1 = row0 + 8;
#pragma unroll
    for (int nt = 0; nt < 16; nt++) {
        const long col = (long)h * DH + nt * 8 + 2 * t;
        const float2 ua = h2f2(o16a[nt][0]);
        const float2 wa = h2f2(o16a[nt][1]);
        const float2 ub = h2f2(o16b[nt][0]);
        const float2 wb = h2f2(o16b[nt][1]);
        const float c00 = (o[nt][0] + ua.x + ub.x) * r0i;
        const float c01 = (o[nt][1] + ua.y + ub.y) * r0i;
        const float c10 = (o[nt][2] + wa.x + wb.x) * r1i;
        const float c11 = (o[nt][3] + wa.y + wb.y) * r1i;
        __half hA, lA, hB, lB;
        split2(c00, hA, lA); split2(c01, hB, lB);
        *(uint32_t*)(Ch + row0 * D_ + col) = packh2(hA, hB);
        *(uint32_t*)(Cl + row0 * D_ + col) = packh2(lA, lB);
        split2(c10, hA, lA); split2(c11, hB, lB);
        *(uint32_t*)(Ch + row1 * D_ + col) = packh2(hA, hB);
        *(uint32_t*)(Cl + row1 * D_ + col) = packh2(lA, lB);
    }
}

// ---------------------------------------------------------------------------
// Fused fp32 -> fp16 hi/lo split for x + 4 weight matrices (one launch).
// ---------------------------------------------------------------------------
__global__ __launch_bounds__(256)
void split_all_kernel(const float* __restrict__ x,
                      const float* __restrict__ qw, const float* __restrict__ kw,
                      const float* __restrict__ vw, const float* __restrict__ ow)
{
    const float* src;
    __half *oh, *ol;
    long n;
    switch (blockIdx.y) {
        case 0: src = x;  oh = g_xh;  ol = g_xl;  n = (long)MROWS * D_; break;
        case 1: src = qw; oh = g_qwh; ol = g_qwl; n = (long)D_ * D_;    break;
        case 2: src = kw; oh = g_kwh; ol = g_kwl; n = (long)D_ * D_;    break;
        case 3: src = vw; oh = g_vwh; ol = g_vwl; n = (long)D_ * D_;    break;
        default: src = ow; oh = g_owh; ol = g_owl; n = (long)D_ * D_;   break;
    }
    const long i = ((long)blockIdx.x * blockDim.x + threadIdx.x) * 4;
    if (i >= n) return;
    float4 v = *(const float4*)(src + i);
    __half h0, l0, h1, l1, h2, l2, h3, l3;
    split2(v.x, h0, l0); split2(v.y, h1, l1);
    split2(v.z, h2, l2); split2(v.w, h3, l3);
    *(uint32_t*)(oh + i)     = packh2(h0, h1);
    *(uint32_t*)(oh + i + 2) = packh2(h2, h3);
    *(uint32_t*)(ol + i)     = packh2(l0, l1);
    *(uint32_t*)(ol + i + 2) = packh2(l2, l3);
}

// ---------------------------------------------------------------------------
// Fused RoPE(+permute, split) for q,k  AND  V transpose/split.
// ---------------------------------------------------------------------------
#define RB ((B_ * H_ * S_ * (DH / 2)) / 256)      // 16384 rope blocks
#define VB ((S_ / 32) * (DH / 32) * (B_ * H_))    // 8192 vtrans blocks

__global__ __launch_bounds__(256)
void rope_vtrans_kernel()
{
    __shared__ float tile[32][33];
    const int bid = blockIdx.x;

    if (bid < RB) {
        const int HALF = DH / 2;
        const long idx = (long)bid * 256 + threadIdx.x;

        const int j = (int)(idx % HALF);
        const int s = (int)((idx / HALF) % S_);
        const int h = (int)((idx / ((long)HALF * S_)) % H_);
        const int b = (int)(idx / ((long)HALF * S_ * H_));

        const long off_in  = ((long)(b * S_ + s)) * D_ + h * DH + j;
        const long off_out = (((long)(b * H_ + h) * S_) + s) * DH + j;

        const float inv = expf(-(float)j * (9.210340371976184f / 64.0f));
        const float th  = (float)s * inv;
        const float c  = cosf(th);
        const float sn = sinf(th);

        const float QS = 0.08838834764831845f * 1.4426950408889634f; // scale*log2e

        {
            const float x1 = g_tq[off_in];
            const float x2 = g_tq[off_in + HALF];
            const float o1 = (x1 * c - x2 * sn) * QS;
            const float o2 = (x2 * c + x1 * sn) * QS;
            __half hh, hl;
            split2(o1, hh, hl); g_qh[off_out] = hh;        g_ql[off_out] = hl;
            split2(o2, hh, hl); g_qh[off_out + HALF] = hh; g_ql[off_out + HALF] = hl;
        }
        {
            const float x1 = g_tk[off_in];
            const float x2 = g_tk[off_in + HALF];
            const float o1 = x1 * c - x2 * sn;
            const float o2 = x2 * c + x1 * sn;
            __half hh, hl;
            split2(o1, hh, hl); g_kh[off_out] = hh;        g_kl[off_out] = hl;
            split2(o2, hh, hl); g_kh[off_out + HALF] = hh; g_kl[off_out + HALF] = hl;
        }
    } else {
        const int vb = bid - RB;
        const int sblk = vb % (S_ / 32);
        const int dblk = (vb / (S_ / 32)) % (DH / 32);
        const int bhz  = vb / ((S_ / 32) * (DH / 32));
        const int b = bhz >> 4, h = bhz & 15;
        const int s0 = sblk * 32, d0 = dblk * 32;
        const int tx = threadIdx.x & 31, ty = threadIdx.x >> 5;

#pragma unroll
        for (int r = 0; r < 4; r++) {
            const int s = s0 + ty + r * 8;
            tile[ty + r * 8][tx] =
                g_tv[((long)b * S_ + s) * D_ + h * DH + d0 + tx];
        }
        __syncthreads();

#pragma unroll
        for (int r = 0; r < 4; r++) {
            const int d = d0 + ty + r * 8;
            const float v = tile[tx][ty + r * 8];
            __half hh, hl;
            split2(v, hh, hl);
            const long off = ((long)bhz * DH + d) * S_ + s0 + tx;
            g_vth[off] = hh;
            g_vtl[off] = hl;
        }
    }
}

// ---------------------------------------------------------------------------
// Launch
// ---------------------------------------------------------------------------
extern "C" void kernel_launch(void* const* d_in, const int* in_sizes, int n_in,
                              void* d_out, int out_size)
{
    const float* x  = (const float*)d_in[0];
    const float* qw = (const float*)d_in[1];
    const float* kw = (const float*)d_in[2];
    const float* vw = (const float*)d_in[3];
    const float* qb = (const float*)d_in[4];
    const float* kb = (const float*)d_in[5];
    const float* vb = (const float*)d_in[6];
    const float* ow = (const float*)d_in[7];
    const float* ob = (const float*)d_in[8];
    float* out = (float*)d_out;

    float *tq, *tk, *tv;
    __half *xh, *xl, *qwh, *qwl, *kwh, *kwl, *vwh, *vwl, *owh, *owl;
    __half *qh, *ql, *kh, *kl, *vth, *vtl, *ctxh, *ctxl;
    cudaGetSymbolAddress((void**)&tq,  g_tq);
    cudaGetSymbolAddress((void**)&tk,  g_tk);
    cudaGetSymbolAddress((void**)&tv,  g_tv);
    cudaGetSymbolAddress((void**)&xh,  g_xh);
    cudaGetSymbolAddress((void**)&xl,  g_xl);
    cudaGetSymbolAddress((void**)&qwh, g_qwh);
    cudaGetSymbolAddress((void**)&qwl, g_qwl);
    cudaGetSymbolAddress((void**)&kwh, g_kwh);
    cudaGetSymbolAddress((void**)&kwl, g_kwl);
    cudaGetSymbolAddress((void**)&vwh, g_vwh);
    cudaGetSymbolAddress((void**)&vwl, g_vwl);
    cudaGetSymbolAddress((void**)&owh, g_owh);
    cudaGetSymbolAddress((void**)&owl, g_owl);
    cudaGetSymbolAddress((void**)&qh,  g_qh);
    cudaGetSymbolAddress((void**)&ql,  g_ql);
    cudaGetSymbolAddress((void**)&kh,  g_kh);
    cudaGetSymbolAddress((void**)&kl,  g_kl);
    cudaGetSymbolAddress((void**)&vth, g_vth);
    cudaGetSymbolAddress((void**)&vtl, g_vtl);
    cudaGetSymbolAddress((void**)&ctxh, g_ctxh);
    cudaGetSymbolAddress((void**)&ctxl, g_ctxl);

    const int SMEM_G = 98304;      // 2 x 48KB stages -> 2 CTAs/SM
    const int SMEM_F = 196608;
    cudaFuncSetAttribute(gemm_hs,      cudaFuncAttributeMaxDynamicSharedMemorySize, SMEM_G);
    cudaFuncSetAttribute(flash_kernel, cudaFuncAttributeMaxDynamicSharedMemorySize, SMEM_F);

    const dim3 blk(256);

    // 0: split fp32 inputs to fp16 hi/lo (one fused launch)
    {
        const long nx = (long)MROWS * D_;
        dim3 grid((unsigned)(nx / 4 / 256), 5);
        split_all_kernel<<<grid, blk>>>(x, qw, kw, vw, ow);
    }

    // 1-3: Q/K/V projections (M=4096, N=2048, K=2048), fp32 out
    {
        dim3 grid(D_ / 64, MROWS / 128, 1);
        gemm_hs<<<grid, blk, SMEM_G>>>(xh, xl, qwh, qwl, tq, D_, D_, qb, 1.0f);
        gemm_hs<<<grid, blk, SMEM_G>>>(xh, xl, kwh, kwl, tk, D_, D_, kb, 1.0f);
        gemm_hs<<<grid, blk, SMEM_G>>>(xh, xl, vwh, vwl, tv, D_, D_, vb, 1.0f);
    }

    // 4: RoPE (q,k) + permute/split  AND  V transpose/split (one launch)
    rope_vtrans_kernel<<<RB + VB, blk>>>();

    // 5: fused flash attention -> ctx split fp16 [B,S,D]
    {
        dim3 grid(S_ / 128, B_ * H_);
        flash_kernel<<<grid, blk, SMEM_F>>>(qh, ql, kh, kl, vth, vtl, ctxh, ctxl);
    }

    // 6: out = ctx @ out_w^T + out_b (fp32 out)
    {
        dim3 grid(D_ / 64, MROWS / 128, 1);
        gemm_hs<<<grid, blk, SMEM_G>>>(ctxh, ctxl, owh, owl, out, D_, D_, ob, 1.0f);
    }
}

// round 13
// speedup vs baseline: 1.0522x; 1.0522x over previous
#include <cuda_runtime.h>
#include <cuda_fp16.h>
#include <cstdint>
#include <math.h>

// Problem constants
#define B_  2
#define S_  2048
#define D_  2048
#define H_  16
#define DH  128
#define MROWS (B_ * S_)          // 4096

// ---------------------------------------------------------------------------
// Scratch (static __device__ arrays; no allocation anywhere)
// ---------------------------------------------------------------------------
__device__ float g_tq[(size_t)MROWS * D_];
__device__ float g_tk[(size_t)MROWS * D_];
__device__ float g_tv[(size_t)MROWS * D_];

__device__ __align__(256) __half g_xh [(size_t)MROWS * D_];
__device__ __align__(256) __half g_xl [(size_t)MROWS * D_];
__device__ __align__(256) __half g_qwh[(size_t)D_ * D_];
__device__ __align__(256) __half g_qwl[(size_t)D_ * D_];
__device__ __align__(256) __half g_kwh[(size_t)D_ * D_];
__device__ __align__(256) __half g_kwl[(size_t)D_ * D_];
__device__ __align__(256) __half g_vwh[(size_t)D_ * D_];
__device__ __align__(256) __half g_vwl[(size_t)D_ * D_];
__device__ __align__(256) __half g_owh[(size_t)D_ * D_];
__device__ __align__(256) __half g_owl[(size_t)D_ * D_];
__device__ __align__(256) __half g_qh [(size_t)B_ * H_ * S_ * DH];
__device__ __align__(256) __half g_ql [(size_t)B_ * H_ * S_ * DH];
__device__ __align__(256) __half g_kh [(size_t)B_ * H_ * S_ * DH];
__device__ __align__(256) __half g_kl [(size_t)B_ * H_ * S_ * DH];
__device__ __align__(256) __half g_vth[(size_t)B_ * H_ * DH * S_];   // V^T [B,H,Dh,S]
__device__ __align__(256) __half g_vtl[(size_t)B_ * H_ * DH * S_];
__device__ __align__(256) __half g_ctxh[(size_t)MROWS * D_];
__device__ __align__(256) __half g_ctxl[(size_t)MROWS * D_];

// ---------------------------------------------------------------------------
// Helpers (all sm_80-era instructions: valid on base sm_103 target)
// ---------------------------------------------------------------------------
#define SWZ(x) ((x) ^ (((x) >> 3) & 0x70))

#define LDSM4(r, addr) \
    asm volatile("ldmatrix.sync.aligned.m8n8.x4.shared.b16 {%0,%1,%2,%3}, [%4];" \
        : "=r"((r)[0]), "=r"((r)[1]), "=r"((r)[2]), "=r"((r)[3]) : "r"(addr))

// fp32-accumulate MMA (main hi*hi pass)
#define MMA(d, a, b0, b1) \
    asm volatile("mma.sync.aligned.m16n8k16.row.col.f32.f16.f16.f32 " \
        "{%0,%1,%2,%3},{%4,%5,%6,%7},{%8,%9},{%0,%1,%2,%3};" \
        : "+f"((d)[0]), "+f"((d)[1]), "+f"((d)[2]), "+f"((d)[3]) \
        : "r"((a)[0]), "r"((a)[1]), "r"((a)[2]), "r"((a)[3]), "r"(b0), "r"(b1))

// fp16-accumulate MMA (2x rate; used for the small correction passes)
#define MMA16(d, a, b0, b1) \
    asm volatile("mma.sync.aligned.m16n8k16.row.col.f16.f16.f16.f16 " \
        "{%0,%1},{%2,%3,%4,%5},{%6,%7},{%0,%1};" \
        : "+r"((d)[0]), "+r"((d)[1]) \
        : "r"((a)[0]), "r"((a)[1]), "r"((a)[2]), "r"((a)[3]), "r"(b0), "r"(b1))

#define CP16(dst, src) \
    asm volatile("cp.async.cg.shared.global [%0], [%1], 16;" :: "r"(dst), "l"(src))
#define CP_COMMIT() asm volatile("cp.async.commit_group;" ::: "memory")
#define CP_WAIT0()  asm volatile("cp.async.wait_group 0;"  ::: "memory")

__device__ __forceinline__ void split2(float x, __half& h, __half& l) {
    h = __float2half(x);
    l = __float2half(x - __half2float(h));
}
__device__ __forceinline__ uint32_t packh2(__half a, __half b) {
    __half2 t; t.x = a; t.y = b;
    return *(uint32_t*)&t;
}
__device__ __forceinline__ float2 h2f2(uint32_t u) {
    return __half22float2(*(__half2*)&u);
}

// Batch descriptor: up to 3 (B, C, bias) sets selected by blockIdx.z
struct GemmBatch {
    const __half* bh[3];
    const __half* bl[3];
    float*        c[3];
    const float*  bias[3];
};

// ---------------------------------------------------------------------------
// fp16-split HMMA GEMM (R10-validated config).  C = scale*(A @ B^T) + bias
//   hi*hi in fp32 accum; hi*lo + lo*hi share one fp16x2 accum (2x-rate MMA).
// Tile 128x128, BK=64; 512 threads / 16 warps of 32x32 (4 warps/SMSP).
// blockIdx.z selects the (B, C, bias) set -> one launch covers Q,K,V.
// smem: 2 stages x [Ah 16K | Al 16K | Bh 16K | Bl 16K] = 128KB.
// ---------------------------------------------------------------------------
__global__ __launch_bounds__(512, 1)
void gemm_hs(const __half* __restrict__ Ah, const __half* __restrict__ Al,
             GemmBatch gb, int K, int ldb, float scale)
{
    extern __shared__ char smem[];
    const uint32_t sb = (uint32_t)__cvta_generic_to_shared(smem);

    const int z = blockIdx.z;
    const __half* __restrict__ Bh = gb.bh[z];
    const __half* __restrict__ Bl = gb.bl[z];
    float* __restrict__ C         = gb.c[z];
    const float* __restrict__ bias = gb.bias[z];

    const int tid = threadIdx.x, wid = tid >> 5, lane = tid & 31;
    const long bm = (long)blockIdx.y * 128;
    const long bn = (long)blockIdx.x * 128;

    // staging: 512 threads; row = tid>>2 (0..127), 2 chunks of 16B each
    const int srow = tid >> 2;
    const int sc0  = (tid & 3) * 2;
    uint32_t soff[2];
#pragma unroll
    for (int i = 0; i < 2; i++)
        soff[i] = SWZ((uint32_t)(srow * 128 + (sc0 + i) * 16));

    const int nk = K / 64;

    // prologue: stage buffer 0
    {
        const __half* pa  = Ah + (bm + srow) * (long)K + sc0 * 8;
        const __half* pl  = Al + (bm + srow) * (long)K + sc0 * 8;
        const __half* pb  = Bh + (bn + srow) * (long)ldb + sc0 * 8;
        const __half* pbl = Bl + (bn + srow) * (long)ldb + sc0 * 8;
#pragma unroll
        for (int i = 0; i < 2; i++) {
            CP16(sb + soff[i],         pa + i * 8);
            CP16(sb + 16384 + soff[i], pl + i * 8);
            CP16(sb + 32768 + soff[i], pb + i * 8);
            CP16(sb + 49152 + soff[i], pbl + i * 8);
        }
        CP_COMMIT();
    }

    float acc[2][4][4];
    uint32_t acc16[2][4][2];
#pragma unroll
    for (int a = 0; a < 2; a++)
#pragma unroll
        for (int b = 0; b < 4; b++) {
#pragma unroll
            for (int c = 0; c < 4; c++) acc[a][b][c] = 0.f;
            acc16[a][b][0] = 0u; acc16[a][b][1] = 0u;
        }

    const int m0 = (wid & 3) * 32;          // 4 warp-rows
    const int n0 = (wid >> 2) * 32;         // 4 warp-cols
    const int rA = lane & 15;
    const int cA = lane >> 4;
    const int rB = ((lane >> 1) & 8) + (lane & 7);
    const int cB = (lane >> 3) & 1;

    for (int kt = 0; kt < nk; ++kt) {
        const int s = kt & 1;
        CP_WAIT0();
        __syncthreads();

        if (kt + 1 < nk) {
            const uint32_t db = sb + (s ^ 1) * 65536;
            const __half* pa  = Ah + (bm + srow) * (long)K + (kt + 1) * 64 + sc0 * 8;
            const __half* pl  = Al + (bm + srow) * (long)K + (kt + 1) * 64 + sc0 * 8;
            const __half* pb  = Bh + (bn + srow) * (long)ldb + (kt + 1) * 64 + sc0 * 8;
            const __half* pbl = Bl + (bn + srow) * (long)ldb + (kt + 1) * 64 + sc0 * 8;
#pragma unroll
            for (int i = 0; i < 2; i++) {
                CP16(db + soff[i],         pa + i * 8);
                CP16(db + 16384 + soff[i], pl + i * 8);
                CP16(db + 32768 + soff[i], pb + i * 8);
                CP16(db + 49152 + soff[i], pbl + i * 8);
            }
            CP_COMMIT();
        }

        const uint32_t ba = sb + (uint32_t)s * 65536;
#pragma unroll
        for (int ks = 0; ks < 4; ks++) {
            uint32_t ah[2][4], al[2][4], bh[2][4], bl[2][4];
#pragma unroll
            for (int mt = 0; mt < 2; mt++) {
                const uint32_t addr = ba +
                    SWZ((uint32_t)((m0 + mt * 16 + rA) * 128 + (ks * 2 + cA) * 16));
                LDSM4(ah[mt], addr);
                LDSM4(al[mt], addr + 16384);
            }
#pragma unroll
            for (int p = 0; p < 2; p++) {
                const uint32_t addr = ba + 32768 +
                    SWZ((uint32_t)((n0 + p * 16 + rB) * 128 + (ks * 2 + cB) * 16));
                LDSM4(bh[p], addr);
                LDSM4(bl[p], addr + 16384);
            }
            // pass 1: hi*hi (fp32 acc)
#pragma unroll
            for (int mt = 0; mt < 2; mt++)
#pragma unroll
                for (int nt = 0; nt < 4; nt++) {
                    const int p = nt >> 1, q = (nt & 1) * 2;
                    MMA(acc[mt][nt], ah[mt], bh[p][q], bh[p][q + 1]);
                }
            // pass 2: hi*lo (fp16 acc)
#pragma unroll
            for (int mt = 0; mt < 2; mt++)
#pragma unroll
                for (int nt = 0; nt < 4; nt++) {
                    const int p = nt >> 1, q = (nt & 1) * 2;
                    MMA16(acc16[mt][nt], ah[mt], bl[p][q], bl[p][q + 1]);
                }
            // pass 3: lo*hi (fp16 acc)
#pragma unroll
            for (int mt = 0; mt < 2; mt++)
#pragma unroll
                for (int nt = 0; nt < 4; nt++) {
                    const int p = nt >> 1, q = (nt & 1) * 2;
                    MMA16(acc16[mt][nt], al[mt], bh[p][q], bh[p][q + 1]);
                }
        }
    }

    const int g = lane >> 2, t = lane & 3;
#pragma unroll
    for (int mt = 0; mt < 2; mt++) {
        const long r0 = bm + m0 + mt * 16 + g;
#pragma unroll
        for (int nt = 0; nt < 4; nt++) {
            const long col = bn + n0 + nt * 8 + 2 * t;
            const float2 u = h2f2(acc16[mt][nt][0]);
            const float2 w = h2f2(acc16[mt][nt][1]);
            float c0 = (acc[mt][nt][0] + u.x) * scale;
            float c1 = (acc[mt][nt][1] + u.y) * scale;
            float c2 = (acc[mt][nt][2] + w.x) * scale;
            float c3 = (acc[mt][nt][3] + w.y) * scale;
            if (bias) {
                const float b0 = __ldg(bias + col), b1 = __ldg(bias + col + 1);
                c0 += b0; c1 += b1; c2 += b0; c3 += b1;
            }
            *(float2*)(C + r0 * (long)D_ + col)       = make_float2(c0, c1);
            *(float2*)(C + (r0 + 8) * (long)D_ + col) = make_float2(c2, c3);
        }
    }
}

// ---------------------------------------------------------------------------
// Flash attention: per CTA = 128 Q rows x one (b,h).  (unchanged from R10)
// smem: Q 64K | Kbuf 2x32K | Vbuf 2x32K = 192K.
// ---------------------------------------------------------------------------
#define NKV (S_ / 64)     // 32 chunks

__global__ __launch_bounds__(256, 1)
void flash_kernel(const __half* __restrict__ Qh, const __half* __restrict__ Ql,
                  const __half* __restrict__ Kh, const __half* __restrict__ Kl,
                  const __half* __restrict__ Vth, const __half* __restrict__ Vtl,
                  __half* __restrict__ Ch, __half* __restrict__ Cl)
{
    extern __shared__ char smem[];
    const uint32_t sb = (uint32_t)__cvta_generic_to_shared(smem);

    const int tid = threadIdx.x, wid = tid >> 5, lane = tid & 31;
    const int qt = blockIdx.x;
    const int bh = blockIdx.y;
    const int b  = bh >> 4, h = bh & 15;

    const __half* Qhp = Qh + ((long)bh * S_ + (long)qt * 128) * DH;
    const __half* Qlp = Ql + ((long)bh * S_ + (long)qt * 128) * DH;
    const __half* Khp = Kh + (long)bh * S_ * DH;
    const __half* Klp = Kl + (long)bh * S_ * DH;
    const __half* Vhp = Vth + (long)bh * DH * S_;
    const __half* Vlp = Vtl + (long)bh * DH * S_;

    const uint32_t KBUF0 = 65536, VBUF0 = 131072;

    {
        const int r = tid >> 1, c0 = (tid & 1) * 8;
        const __half* s1 = Qhp + (long)r * DH;
        const __half* s2 = Qlp + (long)r * DH;
#pragma unroll
        for (int j = 0; j < 8; j++) {
            const int c = c0 + j;
            const uint32_t d = sb + ((c >= 8) ? 16384u : 0u) +
                               SWZ((uint32_t)(r * 128 + (c & 7) * 16));
            CP16(d,          s1 + c * 8);
            CP16(d + 32768u, s2 + c * 8);
        }
    }
    auto stageKV = [&](int it, uint32_t kdst, uint32_t vdst) {
        {
            const int r = tid >> 2, c0 = (tid & 3) * 4;
            const __half* s1 = Khp + ((long)it * 64 + r) * DH;
            const __half* s2 = Klp + ((long)it * 64 + r) * DH;
#pragma unroll
            for (int j = 0; j < 4; j++) {
                const int c = c0 + j;
                const uint32_t d = kdst + ((c >= 8) ? 8192u : 0u) +
                                   SWZ((uint32_t)(r * 128 + (c & 7) * 16));
                CP16(d,          s1 + c * 8);
                CP16(d + 16384u, s2 + c * 8);
            }
        }
        {
            const int dd = tid >> 1, c0 = (tid & 1) * 4;
            const __half* s1 = Vhp + (long)dd * S_ + it * 64;
            const __half* s2 = Vlp + (long)dd * S_ + it * 64;
#pragma unroll
            for (int j = 0; j < 4; j++) {
                const int c = c0 + j;
                const uint32_t d = vdst + SWZ((uint32_t)(dd * 128 + c * 16));
                CP16(d,          s1 + c * 8);
                CP16(d + 16384u, s2 + c * 8);
            }
        }
    };
    stageKV(0, sb + KBUF0, sb + VBUF0);
    CP_COMMIT();

    const int wm = wid * 16;
    const int rA = lane & 15;
    const int cA = lane >> 4;
    const int rB = ((lane >> 1) & 8) + (lane & 7);
    const int cB = (lane >> 3) & 1;
    const int g = lane >> 2, t = lane & 3;

    float o[16][4];
    uint32_t o16a[16][2], o16b[16][2];
#pragma unroll
    for (int i = 0; i < 16; i++) {
#pragma unroll
        for (int j = 0; j < 4; j++) o[i][j] = 0.f;
        o16a[i][0] = 0u; o16a[i][1] = 0u;
        o16b[i][0] = 0u; o16b[i][1] = 0u;
    }
    float m0 = -INFINITY, m1 = -INFINITY, l0 = 0.f, l1 = 0.f;

    for (int it = 0; it < NKV; ++it) {
        const int s = it & 1;
        CP_WAIT0();
        __syncthreads();
        if (it + 1 < NKV) {
            const int s2 = s ^ 1;
            stageKV(it + 1, sb + KBUF0 + s2 * 32768u, sb + VBUF0 + s2 * 32768u);
            CP_COMMIT();
        }

        const uint32_t kbuf = sb + KBUF0 + (uint32_t)s * 32768u;
        const uint32_t vbuf = sb + VBUF0 + (uint32_t)s * 32768u;

        float sa[8][4];
        uint32_t sa16[8][2];
#pragma unroll
        for (int i = 0; i < 8; i++) {
#pragma unroll
            for (int j = 0; j < 4; j++) sa[i][j] = 0.f;
            sa16[i][0] = 0u; sa16[i][1] = 0u;
        }

#pragma unroll
        for (int ks = 0; ks < 8; ks++) {
            uint32_t ah[4], al[4], bh[4][4], bl[4][4];
            const uint32_t qa = sb + (ks >> 2) * 16384u +
                SWZ((uint32_t)((wm + rA) * 128 + ((ks & 3) * 2 + cA) * 16));
            LDSM4(ah, qa);
            LDSM4(al, qa + 32768u);
            const uint32_t kb2 = kbuf + (ks >> 2) * 8192u;
#pragma unroll
            for (int p = 0; p < 4; p++) {
                const uint32_t addr = kb2 +
                    SWZ((uint32_t)((p * 16 + rB) * 128 + ((ks & 3) * 2 + cB) * 16));
                LDSM4(bh[p], addr);
                LDSM4(bl[p], addr + 16384u);
            }
#pragma unroll
            for (int nt = 0; nt < 8; nt++) {
                const int p = nt >> 1, q = (nt & 1) * 2;
                MMA(sa[nt], ah, bh[p][q], bh[p][q + 1]);
            }
#pragma unroll
            for (int nt = 0; nt < 8; nt++) {
                const int p = nt >> 1, q = (nt & 1) * 2;
                MMA16(sa16[nt], ah, bl[p][q], bl[p][q + 1]);
            }
#pragma unroll
            for (int nt = 0; nt < 8; nt++) {
                const int p = nt >> 1, q = (nt & 1) * 2;
                MMA16(sa16[nt], al, bh[p][q], bh[p][q + 1]);
            }
        }

#pragma unroll
        for (int nt = 0; nt < 8; nt++) {
            const float2 u = h2f2(sa16[nt][0]);
            const float2 w = h2f2(sa16[nt][1]);
            sa[nt][0] += u.x; sa[nt][1] += u.y;
            sa[nt][2] += w.x; sa[nt][3] += w.y;
        }

        float nm0 = sa[0][0], nm1 = sa[0][2];
#pragma unroll
        for (int nt = 0; nt < 8; nt++) {
            nm0 = fmaxf(nm0, fmaxf(sa[nt][0], sa[nt][1]));
            nm1 = fmaxf(nm1, fmaxf(sa[nt][2], sa[nt][3]));
        }
        nm0 = fmaxf(nm0, __shfl_xor_sync(0xFFFFFFFFu, nm0, 1));
        nm0 = fmaxf(nm0, __shfl_xor_sync(0xFFFFFFFFu, nm0, 2));
        nm1 = fmaxf(nm1, __shfl_xor_sync(0xFFFFFFFFu, nm1, 1));
        nm1 = fmaxf(nm1, __shfl_xor_sync(0xFFFFFFFFu, nm1, 2));

        const float mn0 = fmaxf(m0, nm0), mn1 = fmaxf(m1, nm1);
        const float al0 = exp2f(m0 - mn0), al1 = exp2f(m1 - mn1);
        m0 = mn0; m1 = mn1;

        float rs0 = 0.f, rs1 = 0.f;
#pragma unroll
        for (int nt = 0; nt < 8; nt++) {
            sa[nt][0] = exp2f(sa[nt][0] - m0);
            sa[nt][1] = exp2f(sa[nt][1] - m0);
            sa[nt][2] = exp2f(sa[nt][2] - m1);
            sa[nt][3] = exp2f(sa[nt][3] - m1);
            rs0 += sa[nt][0] + sa[nt][1];
            rs1 += sa[nt][2] + sa[nt][3];
        }
        rs0 += __shfl_xor_sync(0xFFFFFFFFu, rs0, 1);
        rs0 += __shfl_xor_sync(0xFFFFFFFFu, rs0, 2);
        rs1 += __shfl_xor_sync(0xFFFFFFFFu, rs1, 1);
        rs1 += __shfl_xor_sync(0xFFFFFFFFu, rs1, 2);
        l0 = l0 * al0 + rs0;
        l1 = l1 * al1 + rs1;

        {
            const __half2 a0 = __half2half2(__float2half(al0));
            const __half2 a1 = __half2half2(__float2half(al1));
#pragma unroll
            for (int nt = 0; nt < 16; nt++) {
                o[nt][0] *= al0; o[nt][1] *= al0;
                o[nt][2] *= al1; o[nt][3] *= al1;
                __half2 ta0 = __hmul2(*(__half2*)&o16a[nt][0], a0);
                __half2 ta1 = __hmul2(*(__half2*)&o16a[nt][1], a1);
                __half2 tb0 = __hmul2(*(__half2*)&o16b[nt][0], a0);
                __half2 tb1 = __hmul2(*(__half2*)&o16b[nt][1], a1);
                o16a[nt][0] = *(uint32_t*)&ta0;
                o16a[nt][1] = *(uint32_t*)&ta1;
                o16b[nt][0] = *(uint32_t*)&tb0;
                o16b[nt][1] = *(uint32_t*)&tb1;
            }
        }

#pragma unroll
        for (int kb = 0; kb < 4; kb++) {
            uint32_t aPh[4], aPl[4];
            {
                const float p00 = sa[2 * kb][0],     p01 = sa[2 * kb][1];
                const float p10 = sa[2 * kb][2],     p11 = sa[2 * kb][3];
                const float q00 = sa[2 * kb + 1][0], q01 = sa[2 * kb + 1][1];
                const float q10 = sa[2 * kb + 1][2], q11 = sa[2 * kb + 1][3];
                __half hA, lA, hB, lB;
                split2(p00, hA, lA); split2(p01, hB, lB);
                aPh[0] = packh2(hA, hB); aPl[0] = packh2(lA, lB);
                split2(p10, hA, lA); split2(p11, hB, lB);
                aPh[1] = packh2(hA, hB); aPl[1] = packh2(lA, lB);
                split2(q00, hA, lA); split2(q01, hB, lB);
                aPh[2] = packh2(hA, hB); aPl[2] = packh2(lA, lB);
                split2(q10, hA, lA); split2(q11, hB, lB);
                aPh[3] = packh2(hA, hB); aPl[3] = packh2(lA, lB);
            }
#pragma unroll
            for (int pp = 0; pp < 8; pp++) {
                uint32_t vb[4], vbl[4];
                const uint32_t addr = vbuf +
                    SWZ((uint32_t)((pp * 16 + rB) * 128 + (kb * 2 + cB) * 16));
                LDSM4(vb, addr);
                LDSM4(vbl, addr + 16384u);
                MMA(o[pp * 2], aPh, vb[0], vb[1]);
                MMA16(o16a[pp * 2], aPh, vbl[0], vbl[1]);
                MMA16(o16b[pp * 2], aPl, vb[0], vb[1]);
                MMA(o[pp * 2 + 1], aPh, vb[2], vb[3]);
                MMA16(o16a[pp * 2 + 1], aPh, vbl[2], vbl[3]);
                MMA16(o16b[pp * 2 + 1], aPl, vb[2], vb[3]);
            }
        }
    }

    const float r0i = 1.0f / l0, r1i = 1.0f / l1;
    const long row0 = (long)b * S_ + (long)qt * 128 + wm + g;
    const long row1 = row0 + 8;
#pragma unroll
    for (int nt = 0; nt < 16; nt++) {
        const long col = (long)h * DH + nt * 8 + 2 * t;
        const float2 ua = h2f2(o16a[nt][0]);
        const float2 wa = h2f2(o16a[nt][1]);
        const float2 ub = h2f2(o16b[nt][0]);
        const float2 wb = h2f2(o16b[nt][1]);
        const float c00 = (o[nt][0] + ua.x + ub.x) * r0i;
        const float c01 = (o[nt][1] + ua.y + ub.y) * r0i;
        const float c10 = (o[nt][2] + wa.x + wb.x) * r1i;
        const float c11 = (o[nt][3] + wa.y + wb.y) * r1i;
        __half hA, lA, hB, lB;
        split2(c00, hA, lA); split2(c01, hB, lB);
        *(uint32_t*)(Ch + row0 * D_ + col) = packh2(hA, hB);
        *(uint32_t*)(Cl + row0 * D_ + col) = packh2(lA, lB);
        split2(c10, hA, lA); split2(c11, hB, lB);
        *(uint32_t*)(Ch + row1 * D_ + col) = packh2(hA, hB);
        *(uint32_t*)(Cl + row1 * D_ + col) = packh2(lA, lB);
    }
}

// ---------------------------------------------------------------------------
// Fused fp32 -> fp16 hi/lo split for x + 4 weight matrices (one launch).
// ---------------------------------------------------------------------------
__global__ __launch_bounds__(256)
void split_all_kernel(const float* __restrict__ x,
                      const float* __restrict__ qw, const float* __restrict__ kw,
                      const float* __restrict__ vw, const float* __restrict__ ow)
{
    const float* src;
    __half *oh, *ol;
    long n;
    switch (blockIdx.y) {
        case 0: src = x;  oh = g_xh;  ol = g_xl;  n = (long)MROWS * D_; break;
        case 1: src = qw; oh = g_qwh; ol = g_qwl; n = (long)D_ * D_;    break;
        case 2: src = kw; oh = g_kwh; ol = g_kwl; n = (long)D_ * D_;    break;
        case 3: src = vw; oh = g_vwh; ol = g_vwl; n = (long)D_ * D_;    break;
        default: src = ow; oh = g_owh; ol = g_owl; n = (long)D_ * D_;   break;
    }
    const long i = ((long)blockIdx.x * blockDim.x + threadIdx.x) * 4;
    if (i >= n) return;
    float4 v = *(const float4*)(src + i);
    __half h0, l0, h1, l1, h2, l2, h3, l3;
    split2(v.x, h0, l0); split2(v.y, h1, l1);
    split2(v.z, h2, l2); split2(v.w, h3, l3);
    *(uint32_t*)(oh + i)     = packh2(h0, h1);
    *(uint32_t*)(oh + i + 2) = packh2(h2, h3);
    *(uint32_t*)(ol + i)     = packh2(l0, l1);
    *(uint32_t*)(ol + i + 2) = packh2(l2, l3);
}

// ---------------------------------------------------------------------------
// Fused RoPE(+permute, split) for q,k  AND  V transpose/split.
// ---------------------------------------------------------------------------
#define RB ((B_ * H_ * S_ * (DH / 2)) / 256)      // 16384 rope blocks
#define VB ((S_ / 32) * (DH / 32) * (B_ * H_))    // 8192 vtrans blocks

__global__ __launch_bounds__(256)
void rope_vtrans_kernel()
{
    __shared__ float tile[32][33];
    const int bid = blockIdx.x;

    if (bid < RB) {
        const int HALF = DH / 2;
        const long idx = (long)bid * 256 + threadIdx.x;

        const int j = (int)(idx % HALF);
        const int s = (int)((idx / HALF) % S_);
        const int h = (int)((idx / ((long)HALF * S_)) % H_);
        const int b = (int)(idx / ((long)HALF * S_ * H_));

        const long off_in  = ((long)(b * S_ + s)) * D_ + h * DH + j;
        const long off_out = (((long)(b * H_ + h) * S_) + s) * DH + j;

        const float inv = expf(-(float)j * (9.210340371976184f / 64.0f));
        const float th  = (float)s * inv;
        const float c  = cosf(th);
        const float sn = sinf(th);

        const float QS = 0.08838834764831845f * 1.4426950408889634f; // scale*log2e

        {
            const float x1 = g_tq[off_in];
            const float x2 = g_tq[off_in + HALF];
            const float o1 = (x1 * c - x2 * sn) * QS;
            const float o2 = (x2 * c + x1 * sn) * QS;
            __half hh, hl;
            split2(o1, hh, hl); g_qh[off_out] = hh;        g_ql[off_out] = hl;
            split2(o2, hh, hl); g_qh[off_out + HALF] = hh; g_ql[off_out + HALF] = hl;
        }
        {
            const float x1 = g_tk[off_in];
            const float x2 = g_tk[off_in + HALF];
            const float o1 = x1 * c - x2 * sn;
            const float o2 = x2 * c + x1 * sn;
            __half hh, hl;
            split2(o1, hh, hl); g_kh[off_out] = hh;        g_kl[off_out] = hl;
            split2(o2, hh, hl); g_kh[off_out + HALF] = hh; g_kl[off_out + HALF] = hl;
        }
    } else {
        const int vb = bid - RB;
        const int sblk = vb % (S_ / 32);
        const int dblk = (vb / (S_ / 32)) % (DH / 32);
        const int bhz  = vb / ((S_ / 32) * (DH / 32));
        const int b = bhz >> 4, h = bhz & 15;
        const int s0 = sblk * 32, d0 = dblk * 32;
        const int tx = threadIdx.x & 31, ty = threadIdx.x >> 5;

#pragma unroll
        for (int r = 0; r < 4; r++) {
            const int s = s0 + ty + r * 8;
            tile[ty + r * 8][tx] =
                g_tv[((long)b * S_ + s) * D_ + h * DH + d0 + tx];
        }
        __syncthreads();

#pragma unroll
        for (int r = 0; r < 4; r++) {
            const int d = d0 + ty + r * 8;
            const float v = tile[tx][ty + r * 8];
            __half hh, hl;
            split2(v, hh, hl);
            const long off = ((long)bhz * DH + d) * S_ + s0 + tx;
            g_vth[off] = hh;
            g_vtl[off] = hl;
        }
    }
}

// ---------------------------------------------------------------------------
// Launch
// ---------------------------------------------------------------------------
extern "C" void kernel_launch(void* const* d_in, const int* in_sizes, int n_in,
                              void* d_out, int out_size)
{
    const float* x  = (const float*)d_in[0];
    const float* qw = (const float*)d_in[1];
    const float* kw = (const float*)d_in[2];
    const float* vw = (const float*)d_in[3];
    const float* qb = (const float*)d_in[4];
    const float* kb = (const float*)d_in[5];
    const float* vb = (const float*)d_in[6];
    const float* ow = (const float*)d_in[7];
    const float* ob = (const float*)d_in[8];
    float* out = (float*)d_out;

    float *tq, *tk, *tv;
    __half *xh, *xl, *qwh, *qwl, *kwh, *kwl, *vwh, *vwl, *owh, *owl;
    __half *qh, *ql, *kh, *kl, *vth, *vtl, *ctxh, *ctxl;
    cudaGetSymbolAddress((void**)&tq,  g_tq);
    cudaGetSymbolAddress((void**)&tk,  g_tk);
    cudaGetSymbolAddress((void**)&tv,  g_tv);
    cudaGetSymbolAddress((void**)&xh,  g_xh);
    cudaGetSymbolAddress((void**)&xl,  g_xl);
    cudaGetSymbolAddress((void**)&qwh, g_qwh);
    cudaGetSymbolAddress((void**)&qwl, g_qwl);
    cudaGetSymbolAddress((void**)&kwh, g_kwh);
    cudaGetSymbolAddress((void**)&kwl, g_kwl);
    cudaGetSymbolAddress((void**)&vwh, g_vwh);
    cudaGetSymbolAddress((void**)&vwl, g_vwl);
    cudaGetSymbolAddress((void**)&owh, g_owh);
    cudaGetSymbolAddress((void**)&owl, g_owl);
    cudaGetSymbolAddress((void**)&qh,  g_qh);
    cudaGetSymbolAddress((void**)&ql,  g_ql);
    cudaGetSymbolAddress((void**)&kh,  g_kh);
    cudaGetSymbolAddress((void**)&kl,  g_kl);
    cudaGetSymbolAddress((void**)&vth, g_vth);
    cudaGetSymbolAddress((void**)&vtl, g_vtl);
    cudaGetSymbolAddress((void**)&ctxh, g_ctxh);
    cudaGetSymbolAddress((void**)&ctxl, g_ctxl);

    const int SMEM_G = 131072;
    const int SMEM_F = 196608;
    cudaFuncSetAttribute(gemm_hs,      cudaFuncAttributeMaxDynamicSharedMemorySize, SMEM_G);
    cudaFuncSetAttribute(flash_kernel, cudaFuncAttributeMaxDynamicSharedMemorySize, SMEM_F);

    const dim3 blk(256);
    const dim3 blk_g(512);

    // 0: split fp32 inputs to fp16 hi/lo (one fused launch)
    {
        const long nx = (long)MROWS * D_;
        dim3 grid((unsigned)(nx / 4 / 256), 5);
        split_all_kernel<<<grid, blk>>>(x, qw, kw, vw, ow);
    }

    // 1: Q/K/V projections in ONE launch (grid.z selects weight set)
    {
        GemmBatch gb;
        gb.bh[0] = qwh; gb.bl[0] = qwl; gb.c[0] = tq; gb.bias[0] = qb;
        gb.bh[1] = kwh; gb.bl[1] = kwl; gb.c[1] = tk; gb.bias[1] = kb;
        gb.bh[2] = vwh; gb.bl[2] = vwl; gb.c[2] = tv; gb.bias[2] = vb;
        dim3 grid(D_ / 128, MROWS / 128, 3);
        gemm_hs<<<grid, blk_g, SMEM_G>>>(xh, xl, gb, D_, D_, 1.0f);
    }

    // 2: RoPE (q,k) + permute/split  AND  V transpose/split (one launch)
    rope_vtrans_kernel<<<RB + VB, blk>>>();

    // 3: fused flash attention -> ctx split fp16 [B,S,D]
    {
        dim3 grid(S_ / 128, B_ * H_);
        flash_kernel<<<grid, blk, SMEM_F>>>(qh, ql, kh, kl, vth, vtl, ctxh, ctxl);
    }

    // 4: out = ctx @ out_w^T + out_b (fp32 out)
    {
        GemmBatch gb;
        gb.bh[0] = owh; gb.bl[0] = owl; gb.c[0] = out; gb.bias[0] = ob;
        gb.bh[1] = owh; gb.bl[1] = owl; gb.c[1] = out; gb.bias[1] = ob;
        gb.bh[2] = owh; gb.bl[2] = owl; gb.c[2] = out; gb.bias[2] = ob;
        dim3 grid(D_ / 128, MROWS / 128, 1);
        gemm_hs<<<grid, blk_g, SMEM_G>>>(ctxh, ctxl, gb, D_, D_, 1.0f);
    }
}

// round 14
// speedup vs baseline: 1.1602x; 1.1027x over previous
#include <cuda_runtime.h>
#include <cuda_fp16.h>
#include <cstdint>
#include <math.h>

// Problem constants
#define B_  2
#define S_  2048
#define D_  2048
#define H_  16
#define DH  128
#define MROWS (B_ * S_)          // 4096

// ---------------------------------------------------------------------------
// Scratch (static __device__ arrays; no allocation anywhere)
// ---------------------------------------------------------------------------
__device__ float g_tq[(size_t)MROWS * D_];
__device__ float g_tk[(size_t)MROWS * D_];
__device__ float g_tv[(size_t)MROWS * D_];

__device__ __align__(256) __half g_xh [(size_t)MROWS * D_];
__device__ __align__(256) __half g_xl [(size_t)MROWS * D_];
__device__ __align__(256) __half g_qwh[(size_t)D_ * D_];
__device__ __align__(256) __half g_qwl[(size_t)D_ * D_];
__device__ __align__(256) __half g_kwh[(size_t)D_ * D_];
__device__ __align__(256) __half g_kwl[(size_t)D_ * D_];
__device__ __align__(256) __half g_vwh[(size_t)D_ * D_];
__device__ __align__(256) __half g_vwl[(size_t)D_ * D_];
__device__ __align__(256) __half g_owh[(size_t)D_ * D_];
__device__ __align__(256) __half g_owl[(size_t)D_ * D_];
__device__ __align__(256) __half g_qh [(size_t)B_ * H_ * S_ * DH];
__device__ __align__(256) __half g_ql [(size_t)B_ * H_ * S_ * DH];
__device__ __align__(256) __half g_kh [(size_t)B_ * H_ * S_ * DH];
__device__ __align__(256) __half g_kl [(size_t)B_ * H_ * S_ * DH];
__device__ __align__(256) __half g_vth[(size_t)B_ * H_ * DH * S_];   // V^T [B,H,Dh,S]
__device__ __align__(256) __half g_vtl[(size_t)B_ * H_ * DH * S_];
__device__ __align__(256) __half g_ctxh[(size_t)MROWS * D_];
__device__ __align__(256) __half g_ctxl[(size_t)MROWS * D_];

// ---------------------------------------------------------------------------
// Helpers (all sm_80-era instructions: valid on base sm_103 target)
// ---------------------------------------------------------------------------
#define SWZ(x) ((x) ^ (((x) >> 3) & 0x70))

#define LDSM4(r, addr) \
    asm volatile("ldmatrix.sync.aligned.m8n8.x4.shared.b16 {%0,%1,%2,%3}, [%4];" \
        : "=r"((r)[0]), "=r"((r)[1]), "=r"((r)[2]), "=r"((r)[3]) : "r"(addr))

// fp32-accumulate MMA (all passes: f16-acc has NO rate advantage on sm_103a)
#define MMA(d, a, b0, b1) \
    asm volatile("mma.sync.aligned.m16n8k16.row.col.f32.f16.f16.f32 " \
        "{%0,%1,%2,%3},{%4,%5,%6,%7},{%8,%9},{%0,%1,%2,%3};" \
        : "+f"((d)[0]), "+f"((d)[1]), "+f"((d)[2]), "+f"((d)[3]) \
        : "r"((a)[0]), "r"((a)[1]), "r"((a)[2]), "r"((a)[3]), "r"(b0), "r"(b1))

#define CP16(dst, src) \
    asm volatile("cp.async.cg.shared.global [%0], [%1], 16;" :: "r"(dst), "l"(src))
#define CP_COMMIT() asm volatile("cp.async.commit_group;" ::: "memory")
#define CP_WAIT0()  asm volatile("cp.async.wait_group 0;"  ::: "memory")

__device__ __forceinline__ void split2(float x, __half& h, __half& l) {
    h = __float2half(x);
    l = __float2half(x - __half2float(h));
}
__device__ __forceinline__ uint32_t packh2(__half a, __half b) {
    __half2 t; t.x = a; t.y = b;
    return *(uint32_t*)&t;
}

// Batch descriptor: up to 3 (B, C, bias) sets selected by blockIdx.z
struct GemmBatch {
    const __half* bh[3];
    const __half* bl[3];
    float*        c[3];
    const float*  bias[3];
};

// ---------------------------------------------------------------------------
// fp16-split HMMA GEMM.  C = scale*(A @ B^T) + bias, fp32 out
//   3 passes (hi*hi, hi*lo, lo*hi), ALL f32-acc into the same accumulators.
// Tile 128x128, BK=64; 512 threads / 16 warps of 32x32 (4 warps/SMSP).
// blockIdx.z selects the (B, C, bias) set -> one launch covers Q,K,V.
// smem: 2 stages x [Ah 16K | Al 16K | Bh 16K | Bl 16K] = 128KB.
// ---------------------------------------------------------------------------
__global__ __launch_bounds__(512, 1)
void gemm_hs(const __half* __restrict__ Ah, const __half* __restrict__ Al,
             GemmBatch gb, int K, int ldb, float scale)
{
    extern __shared__ char smem[];
    const uint32_t sb = (uint32_t)__cvta_generic_to_shared(smem);

    const int z = blockIdx.z;
    const __half* __restrict__ Bh = gb.bh[z];
    const __half* __restrict__ Bl = gb.bl[z];
    float* __restrict__ C          = gb.c[z];
    const float* __restrict__ bias = gb.bias[z];

    const int tid = threadIdx.x, wid = tid >> 5, lane = tid & 31;
    const long bm = (long)blockIdx.y * 128;
    const long bn = (long)blockIdx.x * 128;

    const int srow = tid >> 2;
    const int sc0  = (tid & 3) * 2;
    uint32_t soff[2];
#pragma unroll
    for (int i = 0; i < 2; i++)
        soff[i] = SWZ((uint32_t)(srow * 128 + (sc0 + i) * 16));

    const int nk = K / 64;

    // prologue: stage buffer 0
    {
        const __half* pa  = Ah + (bm + srow) * (long)K + sc0 * 8;
        const __half* pl  = Al + (bm + srow) * (long)K + sc0 * 8;
        const __half* pb  = Bh + (bn + srow) * (long)ldb + sc0 * 8;
        const __half* pbl = Bl + (bn + srow) * (long)ldb + sc0 * 8;
#pragma unroll
        for (int i = 0; i < 2; i++) {
            CP16(sb + soff[i],         pa + i * 8);
            CP16(sb + 16384 + soff[i], pl + i * 8);
            CP16(sb + 32768 + soff[i], pb + i * 8);
            CP16(sb + 49152 + soff[i], pbl + i * 8);
        }
        CP_COMMIT();
    }

    float acc[2][4][4];
#pragma unroll
    for (int a = 0; a < 2; a++)
#pragma unroll
        for (int b = 0; b < 4; b++)
#pragma unroll
            for (int c = 0; c < 4; c++) acc[a][b][c] = 0.f;

    const int m0 = (wid & 3) * 32;
    const int n0 = (wid >> 2) * 32;
    const int rA = lane & 15;
    const int cA = lane >> 4;
    const int rB = ((lane >> 1) & 8) + (lane & 7);
    const int cB = (lane >> 3) & 1;

    for (int kt = 0; kt < nk; ++kt) {
        const int s = kt & 1;
        CP_WAIT0();
        __syncthreads();

        if (kt + 1 < nk) {
            const uint32_t db = sb + (s ^ 1) * 65536;
            const __half* pa  = Ah + (bm + srow) * (long)K + (kt + 1) * 64 + sc0 * 8;
            const __half* pl  = Al + (bm + srow) * (long)K + (kt + 1) * 64 + sc0 * 8;
            const __half* pb  = Bh + (bn + srow) * (long)ldb + (kt + 1) * 64 + sc0 * 8;
            const __half* pbl = Bl + (bn + srow) * (long)ldb + (kt + 1) * 64 + sc0 * 8;
#pragma unroll
            for (int i = 0; i < 2; i++) {
                CP16(db + soff[i],         pa + i * 8);
                CP16(db + 16384 + soff[i], pl + i * 8);
                CP16(db + 32768 + soff[i], pb + i * 8);
                CP16(db + 49152 + soff[i], pbl + i * 8);
            }
            CP_COMMIT();
        }

        const uint32_t ba = sb + (uint32_t)s * 65536;
#pragma unroll
        for (int ks = 0; ks < 4; ks++) {
            uint32_t ah[2][4], al[2][4], bh[2][4], bl[2][4];
#pragma unroll
            for (int mt = 0; mt < 2; mt++) {
                const uint32_t addr = ba +
                    SWZ((uint32_t)((m0 + mt * 16 + rA) * 128 + (ks * 2 + cA) * 16));
                LDSM4(ah[mt], addr);
                LDSM4(al[mt], addr + 16384);
            }
#pragma unroll
            for (int p = 0; p < 2; p++) {
                const uint32_t addr = ba + 32768 +
                    SWZ((uint32_t)((n0 + p * 16 + rB) * 128 + (ks * 2 + cB) * 16));
                LDSM4(bh[p], addr);
                LDSM4(bl[p], addr + 16384);
            }
            // pass 1: hi*hi
#pragma unroll
            for (int mt = 0; mt < 2; mt++)
#pragma unroll
                for (int nt = 0; nt < 4; nt++) {
                    const int p = nt >> 1, q = (nt & 1) * 2;
                    MMA(acc[mt][nt], ah[mt], bh[p][q], bh[p][q + 1]);
                }
            // pass 2: hi*lo
#pragma unroll
            for (int mt = 0; mt < 2; mt++)
#pragma unroll
                for (int nt = 0; nt < 4; nt++) {
                    const int p = nt >> 1, q = (nt & 1) * 2;
                    MMA(acc[mt][nt], ah[mt], bl[p][q], bl[p][q + 1]);
                }
            // pass 3: lo*hi
#pragma unroll
            for (int mt = 0; mt < 2; mt++)
#pragma unroll
                for (int nt = 0; nt < 4; nt++) {
                    const int p = nt >> 1, q = (nt & 1) * 2;
                    MMA(acc[mt][nt], al[mt], bh[p][q], bh[p][q + 1]);
                }
        }
    }

    const int g = lane >> 2, t = lane & 3;
#pragma unroll
    for (int mt = 0; mt < 2; mt++) {
        const long r0 = bm + m0 + mt * 16 + g;
#pragma unroll
        for (int nt = 0; nt < 4; nt++) {
            const long col = bn + n0 + nt * 8 + 2 * t;
            float c0 = acc[mt][nt][0] * scale;
            float c1 = acc[mt][nt][1] * scale;
            float c2 = acc[mt][nt][2] * scale;
            float c3 = acc[mt][nt][3] * scale;
            if (bias) {
                const float b0 = __ldg(bias + col), b1 = __ldg(bias + col + 1);
                c0 += b0; c1 += b1; c2 += b0; c3 += b1;
            }
            *(float2*)(C + r0 * (long)D_ + col)       = make_float2(c0, c1);
            *(float2*)(C + (r0 + 8) * (long)D_ + col) = make_float2(c2, c3);
        }
    }
}

// ---------------------------------------------------------------------------
// Flash attention: per CTA = 128 Q rows x one (b,h).
// QK: 3 f32-acc passes (softmax amplifies score error -> keep full split).
// PV: SINGLE pass Ph*Vh (value path; dropped corrections ~3e-4 RMS).
// smem: Q 64K | Kbuf 2x32K | Vbuf 2x16K(hi only) = 160K.
// ---------------------------------------------------------------------------
#define NKV (S_ / 64)     // 32 chunks

__global__ __launch_bounds__(256, 1)
void flash_kernel(const __half* __restrict__ Qh, const __half* __restrict__ Ql,
                  const __half* __restrict__ Kh, const __half* __restrict__ Kl,
                  const __half* __restrict__ Vth,
                  __half* __restrict__ Ch, __half* __restrict__ Cl)
{
    extern __shared__ char smem[];
    const uint32_t sb = (uint32_t)__cvta_generic_to_shared(smem);

    const int tid = threadIdx.x, wid = tid >> 5, lane = tid & 31;
    const int qt = blockIdx.x;
    const int bh = blockIdx.y;
    const int b  = bh >> 4, h = bh & 15;

    const __half* Qhp = Qh + ((long)bh * S_ + (long)qt * 128) * DH;
    const __half* Qlp = Ql + ((long)bh * S_ + (long)qt * 128) * DH;
    const __half* Khp = Kh + (long)bh * S_ * DH;
    const __half* Klp = Kl + (long)bh * S_ * DH;
    const __half* Vhp = Vth + (long)bh * DH * S_;

    const uint32_t KBUF0 = 65536, VBUF0 = 131072;   // V buf: 2 x 16K (hi only)

    {
        const int r = tid >> 1, c0 = (tid & 1) * 8;
        const __half* s1 = Qhp + (long)r * DH;
        const __half* s2 = Qlp + (long)r * DH;
#pragma unroll
        for (int j = 0; j < 8; j++) {
            const int c = c0 + j;
            const uint32_t d = sb + ((c >= 8) ? 16384u : 0u) +
                               SWZ((uint32_t)(r * 128 + (c & 7) * 16));
            CP16(d,          s1 + c * 8);
            CP16(d + 32768u, s2 + c * 8);
        }
    }
    auto stageKV = [&](int it, uint32_t kdst, uint32_t vdst) {
        {
            const int r = tid >> 2, c0 = (tid & 3) * 4;
            const __half* s1 = Khp + ((long)it * 64 + r) * DH;
            const __half* s2 = Klp + ((long)it * 64 + r) * DH;
#pragma unroll
            for (int j = 0; j < 4; j++) {
                const int c = c0 + j;
                const uint32_t d = kdst + ((c >= 8) ? 8192u : 0u) +
                                   SWZ((uint32_t)(r * 128 + (c & 7) * 16));
                CP16(d,          s1 + c * 8);
                CP16(d + 16384u, s2 + c * 8);
            }
        }
        {
            const int dd = tid >> 1, c0 = (tid & 1) * 4;
            const __half* s1 = Vhp + (long)dd * S_ + it * 64;
#pragma unroll
            for (int j = 0; j < 4; j++) {
                const int c = c0 + j;
                const uint32_t d = vdst + SWZ((uint32_t)(dd * 128 + c * 16));
                CP16(d, s1 + c * 8);
            }
        }
    };
    stageKV(0, sb + KBUF0, sb + VBUF0);
    CP_COMMIT();

    const int wm = wid * 16;
    const int rA = lane & 15;
    const int cA = lane >> 4;
    const int rB = ((lane >> 1) & 8) + (lane & 7);
    const int cB = (lane >> 3) & 1;
    const int g = lane >> 2, t = lane & 3;

    float o[16][4];
#pragma unroll
    for (int i = 0; i < 16; i++)
#pragma unroll
        for (int j = 0; j < 4; j++) o[i][j] = 0.f;
    float m0 = -INFINITY, m1 = -INFINITY, l0 = 0.f, l1 = 0.f;

    for (int it = 0; it < NKV; ++it) {
        const int s = it & 1;
        CP_WAIT0();
        __syncthreads();
        if (it + 1 < NKV) {
            const int s2 = s ^ 1;
            stageKV(it + 1, sb + KBUF0 + s2 * 32768u, sb + VBUF0 + s2 * 16384u);
            CP_COMMIT();
        }

        const uint32_t kbuf = sb + KBUF0 + (uint32_t)s * 32768u;
        const uint32_t vbuf = sb + VBUF0 + (uint32_t)s * 16384u;

        // ---- S = Q' K^T (3 f32-acc passes) ----
        float sa[8][4];
#pragma unroll
        for (int i = 0; i < 8; i++)
#pragma unroll
            for (int j = 0; j < 4; j++) sa[i][j] = 0.f;

#pragma unroll
        for (int ks = 0; ks < 8; ks++) {
            uint32_t ah[4], al[4], bh[4][4], bl[4][4];
            const uint32_t qa = sb + (ks >> 2) * 16384u +
                SWZ((uint32_t)((wm + rA) * 128 + ((ks & 3) * 2 + cA) * 16));
            LDSM4(ah, qa);
            LDSM4(al, qa + 32768u);
            const uint32_t kb2 = kbuf + (ks >> 2) * 8192u;
#pragma unroll
            for (int p = 0; p < 4; p++) {
                const uint32_t addr = kb2 +
                    SWZ((uint32_t)((p * 16 + rB) * 128 + ((ks & 3) * 2 + cB) * 16));
                LDSM4(bh[p], addr);
                LDSM4(bl[p], addr + 16384u);
            }
#pragma unroll
            for (int nt = 0; nt < 8; nt++) {
                const int p = nt >> 1, q = (nt & 1) * 2;
                MMA(sa[nt], ah, bh[p][q], bh[p][q + 1]);
            }
#pragma unroll
            for (int nt = 0; nt < 8; nt++) {
                const int p = nt >> 1, q = (nt & 1) * 2;
                MMA(sa[nt], ah, bl[p][q], bl[p][q + 1]);
            }
#pragma unroll
            for (int nt = 0; nt < 8; nt++) {
                const int p = nt >> 1, q = (nt & 1) * 2;
                MMA(sa[nt], al, bh[p][q], bh[p][q + 1]);
            }
        }

        // ---- online softmax (rows g and g+8) ----
        float nm0 = sa[0][0], nm1 = sa[0][2];
#pragma unroll
        for (int nt = 0; nt < 8; nt++) {
            nm0 = fmaxf(nm0, fmaxf(sa[nt][0], sa[nt][1]));
            nm1 = fmaxf(nm1, fmaxf(sa[nt][2], sa[nt][3]));
        }
        nm0 = fmaxf(nm0, __shfl_xor_sync(0xFFFFFFFFu, nm0, 1));
        nm0 = fmaxf(nm0, __shfl_xor_sync(0xFFFFFFFFu, nm0, 2));
        nm1 = fmaxf(nm1, __shfl_xor_sync(0xFFFFFFFFu, nm1, 1));
        nm1 = fmaxf(nm1, __shfl_xor_sync(0xFFFFFFFFu, nm1, 2));

        const float mn0 = fmaxf(m0, nm0), mn1 = fmaxf(m1, nm1);
        const float al0 = exp2f(m0 - mn0), al1 = exp2f(m1 - mn1);
        m0 = mn0; m1 = mn1;

        float rs0 = 0.f, rs1 = 0.f;
#pragma unroll
        for (int nt = 0; nt < 8; nt++) {
            sa[nt][0] = exp2f(sa[nt][0] - m0);
            sa[nt][1] = exp2f(sa[nt][1] - m0);
            sa[nt][2] = exp2f(sa[nt][2] - m1);
            sa[nt][3] = exp2f(sa[nt][3] - m1);
            rs0 += sa[nt][0] + sa[nt][1];
            rs1 += sa[nt][2] + sa[nt][3];
        }
        rs0 += __shfl_xor_sync(0xFFFFFFFFu, rs0, 1);
        rs0 += __shfl_xor_sync(0xFFFFFFFFu, rs0, 2);
        rs1 += __shfl_xor_sync(0xFFFFFFFFu, rs1, 1);
        rs1 += __shfl_xor_sync(0xFFFFFFFFu, rs1, 2);
        l0 = l0 * al0 + rs0;
        l1 = l1 * al1 + rs1;

#pragma unroll
        for (int nt = 0; nt < 16; nt++) {
            o[nt][0] *= al0; o[nt][1] *= al0;
            o[nt][2] *= al1; o[nt][3] *= al1;
        }

        // ---- O += P V  (single hi pass) ----
#pragma unroll
        for (int kb = 0; kb < 4; kb++) {
            uint32_t aPh[4];
            aPh[0] = packh2(__float2half(sa[2 * kb][0]),     __float2half(sa[2 * kb][1]));
            aPh[1] = packh2(__float2half(sa[2 * kb][2]),     __float2half(sa[2 * kb][3]));
            aPh[2] = packh2(__float2half(sa[2 * kb + 1][0]), __float2half(sa[2 * kb + 1][1]));
            aPh[3] = packh2(__float2half(sa[2 * kb + 1][2]), __float2half(sa[2 * kb + 1][3]));
#pragma unroll
            for (int pp = 0; pp < 8; pp++) {
                uint32_t vb[4];
                const uint32_t addr = vbuf +
                    SWZ((uint32_t)((pp * 16 + rB) * 128 + (kb * 2 + cB) * 16));
                LDSM4(vb, addr);
                MMA(o[pp * 2],     aPh, vb[0], vb[1]);
                MMA(o[pp * 2 + 1], aPh, vb[2], vb[3]);
            }
        }
    }

    // ---- epilogue: normalize, split, store [B,S,D] ----
    const float r0i = 1.0f / l0, r1i = 1.0f / l1;
    const long row0 = (long)b * S_ + (long)qt * 128 + wm + g;
    const long row1 = row0 + 8;
#pragma unroll
    for (int nt = 0; nt < 16; nt++) {
        const long col = (long)h * DH + nt * 8 + 2 * t;
        const float c00 = o[nt][0] * r0i, c01 = o[nt][1] * r0i;
        const float c10 = o[nt][2] * r1i, c11 = o[nt][3] * r1i;
        __half hA, lA, hB, lB;
        split2(c00, hA, lA); split2(c01, hB, lB);
        *(uint32_t*)(Ch + row0 * D_ + col) = packh2(hA, hB);
        *(uint32_t*)(Cl + row0 * D_ + col) = packh2(lA, lB);
        split2(c10, hA, lA); split2(c11, hB, lB);
        *(uint32_t*)(Ch + row1 * D_ + col) = packh2(hA, hB);
        *(uint32_t*)(Cl + row1 * D_ + col) = packh2(lA, lB);
    }
}

// ---------------------------------------------------------------------------
// Fused fp32 -> fp16 hi/lo split for x + 4 weight matrices (one launch).
// ---------------------------------------------------------------------------
__global__ __launch_bounds__(256)
void split_all_kernel(const float* __restrict__ x,
                      const float* __restrict__ qw, const float* __restrict__ kw,
                      const float* __restrict__ vw, const float* __restrict__ ow)
{
    const float* src;
    __half *oh, *ol;
    long n;
    switch (blockIdx.y) {
        case 0: src = x;  oh = g_xh;  ol = g_xl;  n = (long)MROWS * D_; break;
        case 1: src = qw; oh = g_qwh; ol = g_qwl; n = (long)D_ * D_;    break;
        case 2: src = kw; oh = g_kwh; ol = g_kwl; n = (long)D_ * D_;    break;
        case 3: src = vw; oh = g_vwh; ol = g_vwl; n = (long)D_ * D_;    break;
        default: src = ow; oh = g_owh; ol = g_owl; n = (long)D_ * D_;   break;
    }
    const long i = ((long)blockIdx.x * blockDim.x + threadIdx.x) * 4;
    if (i >= n) return;
    float4 v = *(const float4*)(src + i);
    __half h0, l0, h1, l1, h2, l2, h3, l3;
    split2(v.x, h0, l0); split2(v.y, h1, l1);
    split2(v.z, h2, l2); split2(v.w, h3, l3);
    *(uint32_t*)(oh + i)     = packh2(h0, h1);
    *(uint32_t*)(oh + i + 2) = packh2(h2, h3);
    *(uint32_t*)(ol + i)     = packh2(l0, l1);
    *(uint32_t*)(ol + i + 2) = packh2(l2, l3);
}

// ---------------------------------------------------------------------------
// Fused RoPE(+permute, split) for q,k  AND  V transpose/split (hi only for V^T).
// ---------------------------------------------------------------------------
#define RB ((B_ * H_ * S_ * (DH / 2)) / 256)      // 16384 rope blocks
#define VB ((S_ / 32) * (DH / 32) * (B_ * H_))    // 8192 vtrans blocks

__global__ __launch_bounds__(256)
void rope_vtrans_kernel()
{
    __shared__ float tile[32][33];
    const int bid = blockIdx.x;

    if (bid < RB) {
        const int HALF = DH / 2;
        const long idx = (long)bid * 256 + threadIdx.x;

        const int j = (int)(idx % HALF);
        const int s = (int)((idx / HALF) % S_);
        const int h = (int)((idx / ((long)HALF * S_)) % H_);
        const int b = (int)(idx / ((long)HALF * S_ * H_));

        const long off_in  = ((long)(b * S_ + s)) * D_ + h * DH + j;
        const long off_out = (((long)(b * H_ + h) * S_) + s) * DH + j;

        const float inv = expf(-(float)j * (9.210340371976184f / 64.0f));
        const float th  = (float)s * inv;
        const float c  = cosf(th);
        const float sn = sinf(th);

        const float QS = 0.08838834764831845f * 1.4426950408889634f; // scale*log2e

        {
            const float x1 = g_tq[off_in];
            const float x2 = g_tq[off_in + HALF];
            const float o1 = (x1 * c - x2 * sn) * QS;
            const float o2 = (x2 * c + x1 * sn) * QS;
            __half hh, hl;
            split2(o1, hh, hl); g_qh[off_out] = hh;        g_ql[off_out] = hl;
            split2(o2, hh, hl); g_qh[off_out + HALF] = hh; g_ql[off_out + HALF] = hl;
        }
        {
            const float x1 = g_tk[off_in];
            const float x2 = g_tk[off_in + HALF];
            const float o1 = x1 * c - x2 * sn;
            const float o2 = x2 * c + x1 * sn;
            __half hh, hl;
            split2(o1, hh, hl); g_kh[off_out] = hh;        g_kl[off_out] = hl;
            split2(o2, hh, hl); g_kh[off_out + HALF] = hh; g_kl[off_out + HALF] = hl;
        }
    } else {
        const int vb = bid - RB;
        const int sblk = vb % (S_ / 32);
        const int dblk = (vb / (S_ / 32)) % (DH / 32);
        const int bhz  = vb / ((S_ / 32) * (DH / 32));
        const int b = bhz >> 4, h = bhz & 15;
        const int s0 = sblk * 32, d0 = dblk * 32;
        const int tx = threadIdx.x & 31, ty = threadIdx.x >> 5;

#pragma unroll
        for (int r = 0; r < 4; r++) {
            const int s = s0 + ty + r * 8;
            tile[ty + r * 8][tx] =
                g_tv[((long)b * S_ + s) * D_ + h * DH + d0 + tx];
        }
        __syncthreads();

#pragma unroll
        for (int r = 0; r < 4; r++) {
            const int d = d0 + ty + r * 8;
            const float v = tile[tx][ty + r * 8];
            const long off = ((long)bhz * DH + d) * S_ + s0 + tx;
            g_vth[off] = __float2half(v);
        }
    }
}

// ---------------------------------------------------------------------------
// Launch
// ---------------------------------------------------------------------------
extern "C" void kernel_launch(void* const* d_in, const int* in_sizes, int n_in,
                              void* d_out, int out_size)
{
    const float* x  = (const float*)d_in[0];
    const float* qw = (const float*)d_in[1];
    const float* kw = (const float*)d_in[2];
    const float* vw = (const float*)d_in[3];
    const float* qb = (const float*)d_in[4];
    const float* kb = (const float*)d_in[5];
    const float* vb = (const float*)d_in[6];
    const float* ow = (const float*)d_in[7];
    const float* ob = (const float*)d_in[8];
    float* out = (float*)d_out;

    float *tq, *tk, *tv;
    __half *xh, *xl, *qwh, *qwl, *kwh, *kwl, *vwh, *vwl, *owh, *owl;
    __half *qh, *ql, *kh, *kl, *vth, *ctxh, *ctxl;
    cudaGetSymbolAddress((void**)&tq,  g_tq);
    cudaGetSymbolAddress((void**)&tk,  g_tk);
    cudaGetSymbolAddress((void**)&tv,  g_tv);
    cudaGetSymbolAddress((void**)&xh,  g_xh);
    cudaGetSymbolAddress((void**)&xl,  g_xl);
    cudaGetSymbolAddress((void**)&qwh, g_qwh);
    cudaGetSymbolAddress((void**)&qwl, g_qwl);
    cudaGetSymbolAddress((void**)&kwh, g_kwh);
    cudaGetSymbolAddress((void**)&kwl, g_kwl);
    cudaGetSymbolAddress((void**)&vwh, g_vwh);
    cudaGetSymbolAddress((void**)&vwl, g_vwl);
    cudaGetSymbolAddress((void**)&owh, g_owh);
    cudaGetSymbolAddress((void**)&owl, g_owl);
    cudaGetSymbolAddress((void**)&qh,  g_qh);
    cudaGetSymbolAddress((void**)&ql,  g_ql);
    cudaGetSymbolAddress((void**)&kh,  g_kh);
    cudaGetSymbolAddress((void**)&kl,  g_kl);
    cudaGetSymbolAddress((void**)&vth, g_vth);
    cudaGetSymbolAddress((void**)&ctxh, g_ctxh);
    cudaGetSymbolAddress((void**)&ctxl, g_ctxl);

    const int SMEM_G = 131072;
    const int SMEM_F = 163840;    // Q 64K + K 2x32K + V 2x16K
    cudaFuncSetAttribute(gemm_hs,      cudaFuncAttributeMaxDynamicSharedMemorySize, SMEM_G);
    cudaFuncSetAttribute(flash_kernel, cudaFuncAttributeMaxDynamicSharedMemorySize, SMEM_F);

    const dim3 blk(256);
    const dim3 blk_g(512);

    // 0: split fp32 inputs to fp16 hi/lo (one fused launch)
    {
        const long nx = (long)MROWS * D_;
        dim3 grid((unsigned)(nx / 4 / 256), 5);
        split_all_kernel<<<grid, blk>>>(x, qw, kw, vw, ow);
    }

    // 1: Q/K/V projections in ONE launch (grid.z selects weight set)
    {
        GemmBatch gb;
        gb.bh[0] = qwh; gb.bl[0] = qwl; gb.c[0] = tq; gb.bias[0] = qb;
        gb.bh[1] = kwh; gb.bl[1] = kwl; gb.c[1] = tk; gb.bias[1] = kb;
        gb.bh[2] = vwh; gb.bl[2] = vwl; gb.c[2] = tv; gb.bias[2] = vb;
        dim3 grid(D_ / 128, MROWS / 128, 3);
        gemm_hs<<<grid, blk_g, SMEM_G>>>(xh, xl, gb, D_, D_, 1.0f);
    }

    // 2: RoPE (q,k) + permute/split  AND  V transpose (one launch)
    rope_vtrans_kernel<<<RB + VB, blk>>>();

    // 3: fused flash attention -> ctx split fp16 [B,S,D]
    {
        dim3 grid(S_ / 128, B_ * H_);
        flash_kernel<<<grid, blk, SMEM_F>>>(qh, ql, kh, kl, vth, ctxh, ctxl);
    }

    // 4: out = ctx @ out_w^T + out_b (fp32 out)
    {
        GemmBatch gb;
        gb.bh[0] = owh; gb.bl[0] = owl; gb.c[0] = out; gb.bias[0] = ob;
        gb.bh[1] = owh; gb.bl[1] = owl; gb.c[1] = out; gb.bias[1] = ob;
        gb.bh[2] = owh; gb.bl[2] = owl; gb.c[2] = out; gb.bias[2] = ob;
        dim3 grid(D_ / 128, MROWS / 128, 1);
        gemm_hs<<<grid, blk_g, SMEM_G>>>(ctxh, ctxl, gb, D_, D_, 1.0f);
    }
}

// round 17
// speedup vs baseline: 1.2844x; 1.1071x over previous
#include <cuda_runtime.h>
#include <cuda_fp16.h>
#include <cstdint>
#include <math.h>

// Problem constants
#define B_  2
#define S_  2048
#define D_  2048
#define H_  16
#define DH  128
#define MROWS (B_ * S_)          // 4096

// ---------------------------------------------------------------------------
// Scratch (static __device__ arrays; no allocation anywhere)
// ---------------------------------------------------------------------------
__device__ float g_tq[(size_t)MROWS * D_];
__device__ float g_tk[(size_t)MROWS * D_];
__device__ float g_tv[(size_t)MROWS * D_];

__device__ __align__(256) __half g_xh [(size_t)MROWS * D_];
__device__ __align__(256) __half g_xl [(size_t)MROWS * D_];
__device__ __align__(256) __half g_qwh[(size_t)D_ * D_];
__device__ __align__(256) __half g_qwl[(size_t)D_ * D_];
__device__ __align__(256) __half g_kwh[(size_t)D_ * D_];
__device__ __align__(256) __half g_kwl[(size_t)D_ * D_];
__device__ __align__(256) __half g_vwh[(size_t)D_ * D_];
__device__ __align__(256) __half g_vwl[(size_t)D_ * D_];
__device__ __align__(256) __half g_owh[(size_t)D_ * D_];
__device__ __align__(256) __half g_owl[(size_t)D_ * D_];
__device__ __align__(256) __half g_qh [(size_t)B_ * H_ * S_ * DH];
__device__ __align__(256) __half g_kh [(size_t)B_ * H_ * S_ * DH];
__device__ __align__(256) __half g_kl [(size_t)B_ * H_ * S_ * DH];
__device__ __align__(256) __half g_vth[(size_t)B_ * H_ * DH * S_];   // V^T [B,H,Dh,S] (hi only)
__device__ __align__(256) __half g_ctxh[(size_t)MROWS * D_];

// ---------------------------------------------------------------------------
// Helpers (all sm_80-era instructions: valid on base sm_103 target)
// ---------------------------------------------------------------------------
#define SWZ(x) ((x) ^ (((x) >> 3) & 0x70))

#define LDSM4(r, addr) \
    asm volatile("ldmatrix.sync.aligned.m8n8.x4.shared.b16 {%0,%1,%2,%3}, [%4];" \
        : "=r"((r)[0]), "=r"((r)[1]), "=r"((r)[2]), "=r"((r)[3]) : "r"(addr))

// fp32-accumulate MMA
#define MMA(d, a, b0, b1) \
    asm volatile("mma.sync.aligned.m16n8k16.row.col.f32.f16.f16.f32 " \
        "{%0,%1,%2,%3},{%4,%5,%6,%7},{%8,%9},{%0,%1,%2,%3};" \
        : "+f"((d)[0]), "+f"((d)[1]), "+f"((d)[2]), "+f"((d)[3]) \
        : "r"((a)[0]), "r"((a)[1]), "r"((a)[2]), "r"((a)[3]), "r"(b0), "r"(b1))

#define CP16(dst, src) \
    asm volatile("cp.async.cg.shared.global [%0], [%1], 16;" :: "r"(dst), "l"(src))
#define CP_COMMIT() asm volatile("cp.async.commit_group;" ::: "memory")
#define CP_WAIT0()  asm volatile("cp.async.wait_group 0;"  ::: "memory")

__device__ __forceinline__ void split2(float x, __half& h, __half& l) {
    h = __float2half(x);
    l = __float2half(x - __half2float(h));
}
__device__ __forceinline__ uint32_t packh2(__half a, __half b) {
    __half2 t; t.x = a; t.y = b;
    return *(uint32_t*)&t;
}

// Batch descriptor: up to 3 (B, C, bias) sets selected by blockIdx.z
struct GemmBatch {
    const __half* bh[3];
    const __half* bl[3];
    float*        c[3];
    const float*  bias[3];
};

// ---------------------------------------------------------------------------
// fp16-split HMMA GEMM.  C = scale*(A @ B^T) + bias, fp32 out
//   NPASS=3: hi*hi + hi*lo + lo*hi (A and B full split precision)
//   NPASS=2: hi*hi + hi*lo (B full precision, A at fp16; Al never touched)
// Tile 128x128, BK=64; 512 threads / 16 warps of 32x32 (4 warps/SMSP).
// blockIdx.z selects the (B, C, bias) set.
// smem: 2 stages x [Ah 16K | Al 16K | Bh 16K | Bl 16K] = 128KB.
// ---------------------------------------------------------------------------
template <int NPASS>
__global__ __launch_bounds__(512, 1)
void gemm_hs(const __half* __restrict__ Ah, const __half* __restrict__ Al,
             GemmBatch gb, int K, int ldb, float scale)
{
    extern __shared__ char smem[];
    const uint32_t sb = (uint32_t)__cvta_generic_to_shared(smem);

    const int z = blockIdx.z;
    const __half* __restrict__ Bh = gb.bh[z];
    const __half* __restrict__ Bl = gb.bl[z];
    float* __restrict__ C          = gb.c[z];
    const float* __restrict__ bias = gb.bias[z];

    const int tid = threadIdx.x, wid = tid >> 5, lane = tid & 31;
    const long bm = (long)blockIdx.y * 128;
    const long bn = (long)blockIdx.x * 128;

    const int srow = tid >> 2;
    const int sc0  = (tid & 3) * 2;
    uint32_t soff[2];
#pragma unroll
    for (int i = 0; i < 2; i++)
        soff[i] = SWZ((uint32_t)(srow * 128 + (sc0 + i) * 16));

    const int nk = K / 64;

    // prologue: stage buffer 0
    {
        const __half* pa  = Ah + (bm + srow) * (long)K + sc0 * 8;
        const __half* pb  = Bh + (bn + srow) * (long)ldb + sc0 * 8;
        const __half* pbl = Bl + (bn + srow) * (long)ldb + sc0 * 8;
#pragma unroll
        for (int i = 0; i < 2; i++) {
            CP16(sb + soff[i],         pa + i * 8);
            CP16(sb + 32768 + soff[i], pb + i * 8);
            CP16(sb + 49152 + soff[i], pbl + i * 8);
        }
        if (NPASS == 3) {
            const __half* pl = Al + (bm + srow) * (long)K + sc0 * 8;
#pragma unroll
            for (int i = 0; i < 2; i++)
                CP16(sb + 16384 + soff[i], pl + i * 8);
        }
        CP_COMMIT();
    }

    float acc[2][4][4];
#pragma unroll
    for (int a = 0; a < 2; a++)
#pragma unroll
        for (int b = 0; b < 4; b++)
#pragma unroll
            for (int c = 0; c < 4; c++) acc[a][b][c] = 0.f;

    const int m0 = (wid & 3) * 32;
    const int n0 = (wid >> 2) * 32;
    const int rA = lane & 15;
    const int cA = lane >> 4;
    const int rB = ((lane >> 1) & 8) + (lane & 7);
    const int cB = (lane >> 3) & 1;

    for (int kt = 0; kt < nk; ++kt) {
        const int s = kt & 1;
        CP_WAIT0();
        __syncthreads();

        if (kt + 1 < nk) {
            const uint32_t db = sb + (s ^ 1) * 65536;
            const __half* pa  = Ah + (bm + srow) * (long)K + (kt + 1) * 64 + sc0 * 8;
            const __half* pb  = Bh + (bn + srow) * (long)ldb + (kt + 1) * 64 + sc0 * 8;
            const __half* pbl = Bl + (bn + srow) * (long)ldb + (kt + 1) * 64 + sc0 * 8;
#pragma unroll
            for (int i = 0; i < 2; i++) {
                CP16(db + soff[i],         pa + i * 8);
                CP16(db + 32768 + soff[i], pb + i * 8);
                CP16(db + 49152 + soff[i], pbl + i * 8);
            }
            if (NPASS == 3) {
                const __half* pl = Al + (bm + srow) * (long)K + (kt + 1) * 64 + sc0 * 8;
#pragma unroll
                for (int i = 0; i < 2; i++)
                    CP16(db + 16384 + soff[i], pl + i * 8);
            }
            CP_COMMIT();
        }

        const uint32_t ba = sb + (uint32_t)s * 65536;
#pragma unroll
        for (int ks = 0; ks < 4; ks++) {
            uint32_t ah[2][4], al[2][4], bh[2][4], bl[2][4];
#pragma unroll
            for (int mt = 0; mt < 2; mt++) {
                const uint32_t addr = ba +
                    SWZ((uint32_t)((m0 + mt * 16 + rA) * 128 + (ks * 2 + cA) * 16));
                LDSM4(ah[mt], addr);
                if (NPASS == 3) LDSM4(al[mt], addr + 16384);
            }
#pragma unroll
            for (int p = 0; p < 2; p++) {
                const uint32_t addr = ba + 32768 +
                    SWZ((uint32_t)((n0 + p * 16 + rB) * 128 + (ks * 2 + cB) * 16));
                LDSM4(bh[p], addr);
                LDSM4(bl[p], addr + 16384);
            }
            // pass 1: hi*hi
#pragma unroll
            for (int mt = 0; mt < 2; mt++)
#pragma unroll
                for (int nt = 0; nt < 4; nt++) {
                    const int p = nt >> 1, q = (nt & 1) * 2;
                    MMA(acc[mt][nt], ah[mt], bh[p][q], bh[p][q + 1]);
                }
            // pass 2: hi*lo
#pragma unroll
            for (int mt = 0; mt < 2; mt++)
#pragma unroll
                for (int nt = 0; nt < 4; nt++) {
                    const int p = nt >> 1, q = (nt & 1) * 2;
                    MMA(acc[mt][nt], ah[mt], bl[p][q], bl[p][q + 1]);
                }
            // pass 3: lo*hi
            if (NPASS == 3) {
#pragma unroll
                for (int mt = 0; mt < 2; mt++)
#pragma unroll
                    for (int nt = 0; nt < 4; nt++) {
                        const int p = nt >> 1, q = (nt & 1) * 2;
                        MMA(acc[mt][nt], al[mt], bh[p][q], bh[p][q + 1]);
                    }
            }
        }
    }

    const int g = lane >> 2, t = lane & 3;
#pragma unroll
    for (int mt = 0; mt < 2; mt++) {
        const long r0 = bm + m0 + mt * 16 + g;
#pragma unroll
        for (int nt = 0; nt < 4; nt++) {
            const long col = bn + n0 + nt * 8 + 2 * t;
            float c0 = acc[mt][nt][0] * scale;
            float c1 = acc[mt][nt][1] * scale;
            float c2 = acc[mt][nt][2] * scale;
            float c3 = acc[mt][nt][3] * scale;
            if (bias) {
                const float b0 = __ldg(bias + col), b1 = __ldg(bias + col + 1);
                c0 += b0; c1 += b1; c2 += b0; c3 += b1;
            }
            *(float2*)(C + r0 * (long)D_ + col)       = make_float2(c0, c1);
            *(float2*)(C + (r0 + 8) * (long)D_ + col) = make_float2(c2, c3);
        }
    }
}

// ---------------------------------------------------------------------------
// Flash attention: per CTA = 128 Q rows x one (b,h).
// QK: 2 passes Qh*Kh + Qh*Kl (K full precision, Q fp16).
// PV: single pass Ph*Vh.
// smem: Qh 32K | Kbuf 2x32K | Vbuf 2x16K = 128K.
// ---------------------------------------------------------------------------
#define NKV (S_ / 64)     // 32 chunks

__global__ __launch_bounds__(256, 1)
void flash_kernel(const __half* __restrict__ Qh,
                  const __half* __restrict__ Kh, const __half* __restrict__ Kl,
                  const __half* __restrict__ Vth,
                  __half* __restrict__ Ch)
{
    extern __shared__ char smem[];
    const uint32_t sb = (uint32_t)__cvta_generic_to_shared(smem);

    const int tid = threadIdx.x, wid = tid >> 5, lane = tid & 31;
    const int qt = blockIdx.x;
    const int bh = blockIdx.y;
    const int b  = bh >> 4, h = bh & 15;

    const __half* Qhp = Qh + ((long)bh * S_ + (long)qt * 128) * DH;
    const __half* Khp = Kh + (long)bh * S_ * DH;
    const __half* Klp = Kl + (long)bh * S_ * DH;
    const __half* Vhp = Vth + (long)bh * DH * S_;

    const uint32_t KBUF0 = 32768, VBUF0 = 98304;

    // ---- stage Q (hi only) ----
    {
        const int r = tid >> 1, c0 = (tid & 1) * 8;
        const __half* s1 = Qhp + (long)r * DH;
#pragma unroll
        for (int j = 0; j < 8; j++) {
            const int c = c0 + j;
            const uint32_t d = sb + ((c >= 8) ? 16384u : 0u) +
                               SWZ((uint32_t)(r * 128 + (c & 7) * 16));
            CP16(d, s1 + c * 8);
        }
    }
    auto stageKV = [&](int it, uint32_t kdst, uint32_t vdst) {
        {
            const int r = tid >> 2, c0 = (tid & 3) * 4;
            const __half* s1 = Khp + ((long)it * 64 + r) * DH;
            const __half* s2 = Klp + ((long)it * 64 + r) * DH;
#pragma unroll
            for (int j = 0; j < 4; j++) {
                const int c = c0 + j;
                const uint32_t d = kdst + ((c >= 8) ? 8192u : 0u) +
                                   SWZ((uint32_t)(r * 128 + (c & 7) * 16));
                CP16(d,          s1 + c * 8);
                CP16(d + 16384u, s2 + c * 8);
            }
        }
        {
            const int dd = tid >> 1, c0 = (tid & 1) * 4;
            const __half* s1 = Vhp + (long)dd * S_ + it * 64;
#pragma unroll
            for (int j = 0; j < 4; j++) {
                const int c = c0 + j;
                const uint32_t d = vdst + SWZ((uint32_t)(dd * 128 + c * 16));
                CP16(d, s1 + c * 8);
            }
        }
    };
    stageKV(0, sb + KBUF0, sb + VBUF0);
    CP_COMMIT();

    const int wm = wid * 16;
    const int rA = lane & 15;
    const int cA = lane >> 4;
    const int rB = ((lane >> 1) & 8) + (lane & 7);
    const int cB = (lane >> 3) & 1;
    const int g = lane >> 2, t = lane & 3;

    float o[16][4];
#pragma unroll
    for (int i = 0; i < 16; i++)
#pragma unroll
        for (int j = 0; j < 4; j++) o[i][j] = 0.f;
    float m0 = -INFINITY, m1 = -INFINITY, l0 = 0.f, l1 = 0.f;

    for (int it = 0; it < NKV; ++it) {
        const int s = it & 1;
        CP_WAIT0();
        __syncthreads();
        if (it + 1 < NKV) {
            const int s2 = s ^ 1;
            stageKV(it + 1, sb + KBUF0 + s2 * 32768u, sb + VBUF0 + s2 * 16384u);
            CP_COMMIT();
        }

        const uint32_t kbuf = sb + KBUF0 + (uint32_t)s * 32768u;
        const uint32_t vbuf = sb + VBUF0 + (uint32_t)s * 16384u;

        // ---- S = Q' K^T (2 passes: Qh*Kh + Qh*Kl) ----
        float sa[8][4];
#pragma unroll
        for (int i = 0; i < 8; i++)
#pragma unroll
            for (int j = 0; j < 4; j++) sa[i][j] = 0.f;

#pragma unroll
        for (int ks = 0; ks < 8; ks++) {
            uint32_t ah[4], bh[4][4], bl[4][4];
            const uint32_t qa = sb + (ks >> 2) * 16384u +
                SWZ((uint32_t)((wm + rA) * 128 + ((ks & 3) * 2 + cA) * 16));
            LDSM4(ah, qa);
            const uint32_t kb2 = kbuf + (ks >> 2) * 8192u;
#pragma unroll
            for (int p = 0; p < 4; p++) {
                const uint32_t addr = kb2 +
                    SWZ((uint32_t)((p * 16 + rB) * 128 + ((ks & 3) * 2 + cB) * 16));
                LDSM4(bh[p], addr);
                LDSM4(bl[p], addr + 16384u);
            }
#pragma unroll
            for (int nt = 0; nt < 8; nt++) {
                const int p = nt >> 1, q = (nt & 1) * 2;
                MMA(sa[nt], ah, bh[p][q], bh[p][q + 1]);
            }
#pragma unroll
            for (int nt = 0; nt < 8; nt++) {
                const int p = nt >> 1, q = (nt & 1) * 2;
                MMA(sa[nt], ah, bl[p][q], bl[p][q + 1]);
            }
        }

        // ---- online softmax (rows g and g+8) ----
        float nm0 = sa[0][0], nm1 = sa[0][2];
#pragma unroll
        for (int nt = 0; nt < 8; nt++) {
            nm0 = fmaxf(nm0, fmaxf(sa[nt][0], sa[nt][1]));
            nm1 = fmaxf(nm1, fmaxf(sa[nt][2], sa[nt][3]));
        }
        nm0 = fmaxf(nm0, __shfl_xor_sync(0xFFFFFFFFu, nm0, 1));
        nm0 = fmaxf(nm0, __shfl_xor_sync(0xFFFFFFFFu, nm0, 2));
        nm1 = fmaxf(nm1, __shfl_xor_sync(0xFFFFFFFFu, nm1, 1));
        nm1 = fmaxf(nm1, __shfl_xor_sync(0xFFFFFFFFu, nm1, 2));

        const float mn0 = fmaxf(m0, nm0), mn1 = fmaxf(m1, nm1);
        const float al0 = exp2f(m0 - mn0), al1 = exp2f(m1 - mn1);
        m0 = mn0; m1 = mn1;

        float rs0 = 0.f, rs1 = 0.f;
#pragma unroll
        for (int nt = 0; nt < 8; nt++) {
            sa[nt][0] = exp2f(sa[nt][0] - m0);
            sa[nt][1] = exp2f(sa[nt][1] - m0);
            sa[nt][2] = exp2f(sa[nt][2] - m1);
            sa[nt][3] = exp2f(sa[nt][3] - m1);
            rs0 += sa[nt][0] + sa[nt][1];
            rs1 += sa[nt][2] + sa[nt][3];
        }
        rs0 += __shfl_xor_sync(0xFFFFFFFFu, rs0, 1);
        rs0 += __shfl_xor_sync(0xFFFFFFFFu, rs0, 2);
        rs1 += __shfl_xor_sync(0xFFFFFFFFu, rs1, 1);
        rs1 += __shfl_xor_sync(0xFFFFFFFFu, rs1, 2);
        l0 = l0 * al0 + rs0;
        l1 = l1 * al1 + rs1;

#pragma unroll
        for (int nt = 0; nt < 16; nt++) {
            o[nt][0] *= al0; o[nt][1] *= al0;
            o[nt][2] *= al1; o[nt][3] *= al1;
        }

        // ---- O += P V  (single hi pass) ----
#pragma unroll
        for (int kb = 0; kb < 4; kb++) {
            uint32_t aPh[4];
            aPh[0] = packh2(__float2half(sa[2 * kb][0]),     __float2half(sa[2 * kb][1]));
            aPh[1] = packh2(__float2half(sa[2 * kb][2]),     __float2half(sa[2 * kb][3]));
            aPh[2] = packh2(__float2half(sa[2 * kb + 1][0]), __float2half(sa[2 * kb + 1][1]));
            aPh[3] = packh2(__float2half(sa[2 * kb + 1][2]), __float2half(sa[2 * kb + 1][3]));
#pragma unroll
            for (int pp = 0; pp < 8; pp++) {
                uint32_t vb[4];
                const uint32_t addr = vbuf +
                    SWZ((uint32_t)((pp * 16 + rB) * 128 + (kb * 2 + cB) * 16));
                LDSM4(vb, addr);
                MMA(o[pp * 2],     aPh, vb[0], vb[1]);
                MMA(o[pp * 2 + 1], aPh, vb[2], vb[3]);
            }
        }
    }

    // ---- epilogue: normalize, fp16 store (hi only; out-GEMM uses 2-pass) ----
    const float r0i = 1.0f / l0, r1i = 1.0f / l1;
    const long row0 = (long)b * S_ + (long)qt * 128 + wm + g;
    const long row1 = row0 + 8;
#pragma unroll
    for (int nt = 0; nt < 16; nt++) {
        const long col = (long)h * DH + nt * 8 + 2 * t;
        *(uint32_t*)(Ch + row0 * D_ + col) =
            packh2(__float2half(o[nt][0] * r0i), __float2half(o[nt][1] * r0i));
        *(uint32_t*)(Ch + row1 * D_ + col) =
            packh2(__float2half(o[nt][2] * r1i), __float2half(o[nt][3] * r1i));
    }
}

// ---------------------------------------------------------------------------
// Fused fp32 -> fp16 hi/lo split for x + 4 weight matrices (one launch).
// ---------------------------------------------------------------------------
__global__ __launch_bounds__(256)
void split_all_kernel(const float* __restrict__ x,
                      const float* __restrict__ qw, const float* __restrict__ kw,
                      const float* __restrict__ vw, const float* __restrict__ ow)
{
    const float* src;
    __half *oh, *ol;
    long n;
    switch (blockIdx.y) {
        case 0: src = x;  oh = g_xh;  ol = g_xl;  n = (long)MROWS * D_; break;
        case 1: src = qw; oh = g_qwh; ol = g_qwl; n = (long)D_ * D_;    break;
        case 2: src = kw; oh = g_kwh; ol = g_kwl; n = (long)D_ * D_;    break;
        case 3: src = vw; oh = g_vwh; ol = g_vwl; n = (long)D_ * D_;    break;
        default: src = ow; oh = g_owh; ol = g_owl; n = (long)D_ * D_;   break;
    }
    const long i = ((long)blockIdx.x * blockDim.x + threadIdx.x) * 4;
    if (i >= n) return;
    float4 v = *(const float4*)(src + i);
    __half h0, l0, h1, l1, h2, l2, h3, l3;
    split2(v.x, h0, l0); split2(v.y, h1, l1);
    split2(v.z, h2, l2); split2(v.w, h3, l3);
    *(uint32_t*)(oh + i)     = packh2(h0, h1);
    *(uint32_t*)(oh + i + 2) = packh2(h2, h3);
    *(uint32_t*)(ol + i)     = packh2(l0, l1);
    *(uint32_t*)(ol + i + 2) = packh2(l2, l3);
}

// ---------------------------------------------------------------------------
// Fused RoPE(+permute) for q (hi only) and k (hi/lo), AND V transpose (hi).
// ---------------------------------------------------------------------------
#define RB ((B_ * H_ * S_ * (DH / 2)) / 256)      // 16384 rope blocks
#define VB ((S_ / 32) * (DH / 32) * (B_ * H_))    // 8192 vtrans blocks

__global__ __launch_bounds__(256)
void rope_vtrans_kernel()
{
    __shared__ float tile[32][33];
    const int bid = blockIdx.x;

    if (bid < RB) {
        const int HALF = DH / 2;
        const long idx = (long)bid * 256 + threadIdx.x;

        const int j = (int)(idx % HALF);
        const int s = (int)((idx / HALF) % S_);
        const int h = (int)((idx / ((long)HALF * S_)) % H_);
        const int b = (int)(idx / ((long)HALF * S_ * H_));

        const long off_in  = ((long)(b * S_ + s)) * D_ + h * DH + j;
        const long off_out = (((long)(b * H_ + h) * S_) + s) * DH + j;

        const float inv = expf(-(float)j * (9.210340371976184f / 64.0f));
        const float th  = (float)s * inv;
        const float c  = cosf(th);
        const float sn = sinf(th);

        const float QS = 0.08838834764831845f * 1.4426950408889634f; // scale*log2e

        {
            const float x1 = g_tq[off_in];
            const float x2 = g_tq[off_in + HALF];
            const float o1 = (x1 * c - x2 * sn) * QS;
            const float o2 = (x2 * c + x1 * sn) * QS;
            g_qh[off_out]        = __float2half(o1);
            g_qh[off_out + HALF] = __float2half(o2);
        }
        {
            const float x1 = g_tk[off_in];
            const float x2 = g_tk[off_in + HALF];
            const float o1 = x1 * c - x2 * sn;
            const float o2 = x2 * c + x1 * sn;
            __half hh, hl;
            split2(o1, hh, hl); g_kh[off_out] = hh;        g_kl[off_out] = hl;
            split2(o2, hh, hl); g_kh[off_out + HALF] = hh; g_kl[off_out + HALF] = hl;
        }
    } else {
        const int vb = bid - RB;
        const int sblk = vb % (S_ / 32);
        const int dblk = (vb / (S_ / 32)) % (DH / 32);
        const int bhz  = vb / ((S_ / 32) * (DH / 32));
        const int b = bhz >> 4, h = bhz & 15;
        const int s0 = sblk * 32, d0 = dblk * 32;
        const int tx = threadIdx.x & 31, ty = threadIdx.x >> 5;

#pragma unroll
        for (int r = 0; r < 4; r++) {
            const int s = s0 + ty + r * 8;
            tile[ty + r * 8][tx] =
                g_tv[((long)b * S_ + s) * D_ + h * DH + d0 + tx];
        }
        __syncthreads();

#pragma unroll
        for (int r = 0; r < 4; r++) {
            const int d = d0 + ty + r * 8;
            const float v = tile[tx][ty + r * 8];
            const long off = ((long)bhz * DH + d) * S_ + s0 + tx;
            g_vth[off] = __float2half(v);
        }
    }
}

// ---------------------------------------------------------------------------
// Launch
// ---------------------------------------------------------------------------
extern "C" void kernel_launch(void* const* d_in, const int* in_sizes, int n_in,
                              void* d_out, int out_size)
{
    const float* x  = (const float*)d_in[0];
    const float* qw = (const float*)d_in[1];
    const float* kw = (const float*)d_in[2];
    const float* vw = (const float*)d_in[3];
    const float* qb = (const float*)d_in[4];
    const float* kb = (const float*)d_in[5];
    const float* vb = (const float*)d_in[6];
    const float* ow = (const float*)d_in[7];
    const float* ob = (const float*)d_in[8];
    float* out = (float*)d_out;

    float *tq, *tk, *tv;
    __half *xh, *xl, *qwh, *qwl, *kwh, *kwl, *vwh, *vwl, *owh, *owl;
    __half *qh, *kh, *kl, *vth, *ctxh;
    cudaGetSymbolAddress((void**)&tq,  g_tq);
    cudaGetSymbolAddress((void**)&tk,  g_tk);
    cudaGetSymbolAddress((void**)&tv,  g_tv);
    cudaGetSymbolAddress((void**)&xh,  g_xh);
    cudaGetSymbolAddress((void**)&xl,  g_xl);
    cudaGetSymbolAddress((void**)&qwh, g_qwh);
    cudaGetSymbolAddress((void**)&qwl, g_qwl);
    cudaGetSymbolAddress((void**)&kwh, g_kwh);
    cudaGetSymbolAddress((void**)&kwl, g_kwl);
    cudaGetSymbolAddress((void**)&vwh, g_vwh);
    cudaGetSymbolAddress((void**)&vwl, g_vwl);
    cudaGetSymbolAddress((void**)&owh, g_owh);
    cudaGetSymbolAddress((void**)&owl, g_owl);
    cudaGetSymbolAddress((void**)&qh,  g_qh);
    cudaGetSymbolAddress((void**)&kh,  g_kh);
    cudaGetSymbolAddress((void**)&kl,  g_kl);
    cudaGetSymbolAddress((void**)&vth, g_vth);
    cudaGetSymbolAddress((void**)&ctxh, g_ctxh);

    const int SMEM_G = 131072;
    const int SMEM_F = 131072;    // Qh 32K + K 2x32K + V 2x16K
    cudaFuncSetAttribute(gemm_hs<3>,   cudaFuncAttributeMaxDynamicSharedMemorySize, SMEM_G);
    cudaFuncSetAttribute(gemm_hs<2>,   cudaFuncAttributeMaxDynamicSharedMemorySize, SMEM_G);
    cudaFuncSetAttribute(flash_kernel, cudaFuncAttributeMaxDynamicSharedMemorySize, SMEM_F);

    const dim3 blk(256);
    const dim3 blk_g(512);

    // 0: split fp32 inputs to fp16 hi/lo (one fused launch)
    {
        const long nx = (long)MROWS * D_;
        dim3 grid((unsigned)(nx / 4 / 256), 5);
        split_all_kernel<<<grid, blk>>>(x, qw, kw, vw, ow);
    }

    // 1: Q/K/V projections in ONE launch (grid.z selects weight set), 3-pass
    {
        GemmBatch gb;
        gb.bh[0] = qwh; gb.bl[0] = qwl; gb.c[0] = tq; gb.bias[0] = qb;
        gb.bh[1] = kwh; gb.bl[1] = kwl; gb.c[1] = tk; gb.bias[1] = kb;
        gb.bh[2] = vwh; gb.bl[2] = vwl; gb.c[2] = tv; gb.bias[2] = vb;
        dim3 grid(D_ / 128, MROWS / 128, 3);
        gemm_hs<3><<<grid, blk_g, SMEM_G>>>(xh, xl, gb, D_, D_, 1.0f);
    }

    // 2: RoPE (q hi, k hi/lo) + V transpose (one launch)
    rope_vtrans_kernel<<<RB + VB, blk>>>();

    // 3: fused flash attention -> ctx fp16 [B,S,D]
    {
        dim3 grid(S_ / 128, B_ * H_);
        flash_kernel<<<grid, blk, SMEM_F>>>(qh, kh, kl, vth, ctxh);
    }

    // 4: out = ctx @ out_w^T + out_b (fp32 out), 2-pass (W full precision)
    {
        GemmBatch gb;
        gb.bh[0] = owh; gb.bl[0] = owl; gb.c[0] = out; gb.bias[0] = ob;
        gb.bh[1] = owh; gb.bl[1] = owl; gb.c[1] = out; gb.bias[1] = ob;
        gb.bh[2] = owh; gb.bl[2] = owl; gb.c[2] = out; gb.bias[2] = ob;
        dim3 grid(D_ / 128, MROWS / 128, 1);
        gemm_hs<2><<<grid, blk_g, SMEM_G>>>(ctxh, nullptr, gb, D_, D_, 1.0f);
    }
}